// round 10
// baseline (speedup 1.0000x reference)
#include <cuda_runtime.h>
#include <cuda_bf16.h>
#include <math.h>
#include <float.h>
#include <stdint.h>

#define CH    64
#define IMG_W 256
#define IMG_H 256
#define HWN   65536
#define NB    8
#define PADW  258

// ---------------- device-global scratch -------------------------------------
__device__ __align__(16) __nv_bfloat16 g_padx[NB * PADW * PADW * 128];
__device__ __align__(16) __nv_bfloat16 g_pad1[NB * PADW * PADW * 128];
__device__ __align__(16) __nv_bfloat16 g_rcl [NB * HWN * 128];
__device__ __align__(16) float g_avg[NB * HWN];
__device__ __align__(16) float g_max[NB * HWN];
__device__ __align__(16) float g_sg [NB * HWN];
__device__ float g_chansum[NB * CH];
__device__ __align__(16) __nv_bfloat16 g_Kpk[NB * 2 * 64 * 128];
__device__ __align__(16) uint32_t g_Wfrag[73728];   // [cv][t][wn][sb][ks][h][lane][e]

// ---------------- helpers ----------------------------------------------------
__device__ __forceinline__ int reflect(int v, int n) {
    if (v < 0) v = -v;
    if (v >= n) v = 2 * n - 2 - v;
    return v;
}
__device__ __forceinline__ uint32_t s2u(const void* p) {
    return (uint32_t)__cvta_generic_to_shared(p);
}
__device__ __forceinline__ uint32_t pack2bf(float a, float b) {
    return ((uint32_t)__bfloat16_as_ushort(__float2bfloat16(a))) |
           ((uint32_t)__bfloat16_as_ushort(__float2bfloat16(b)) << 16);
}
__device__ __forceinline__ void ldsm_x4(uint32_t addr, uint32_t& r0, uint32_t& r1,
                                        uint32_t& r2, uint32_t& r3) {
    asm volatile("ldmatrix.sync.aligned.m8n8.x4.shared.b16 {%0,%1,%2,%3}, [%4];"
                 : "=r"(r0), "=r"(r1), "=r"(r2), "=r"(r3) : "r"(addr));
}
__device__ __forceinline__ void mma16816(float* c, const uint32_t* a,
                                         uint32_t b0, uint32_t b1) {
    asm volatile("mma.sync.aligned.m16n8k16.row.col.f32.bf16.bf16.f32 "
                 "{%0,%1,%2,%3}, {%4,%5,%6,%7}, {%8,%9}, {%0,%1,%2,%3};"
                 : "+f"(c[0]), "+f"(c[1]), "+f"(c[2]), "+f"(c[3])
                 : "r"(a[0]), "r"(a[1]), "r"(a[2]), "r"(a[3]), "r"(b0), "r"(b1));
}
__device__ __forceinline__ void cp16(uint32_t dst, const void* src) {
    asm volatile("cp.async.ca.shared.global [%0], [%1], 16;" :: "r"(dst), "l"(src));
}
#define CP_COMMIT() asm volatile("cp.async.commit_group;" ::: "memory")
#define CP_WAIT0()  asm volatile("cp.async.wait_group 0;" ::: "memory")
#define CP_WAIT1()  asm volatile("cp.async.wait_group 1;" ::: "memory")

// ---------------- init ----------------
__global__ void init_kernel() {
    int i = blockIdx.x * blockDim.x + threadIdx.x;
    if (i < NB * CH) g_chansum[i] = 0.0f;
}

// ---------------- weight frag prepack (lane-fastest, coalesced) --------------
__global__ __launch_bounds__(256)
void wfrag_kernel(const float* __restrict__ w1, const float* __restrict__ w2) {
    int idx = blockIdx.x * 256 + threadIdx.x;
    if (idx >= 73728) return;
    int e    = idx & 3;
    int lane = (idx >> 2) & 31;
    int h    = (idx >> 7) & 1;
    int ks   = (idx >> 8) & 3;
    int sb   = (idx >> 10) & 1;
    int wn   = (idx >> 11) & 1;
    int rest = idx >> 12;
    int t    = rest % 9;
    int cv   = rest / 9;
    int nt = 2 * h + (e >> 1);
    int rr = e & 1;
    int n  = wn * 32 + nt * 8 + (lane >> 2);
    int k0 = ks * 16 + rr * 8 + (lane & 3) * 2;
    const float* w = cv ? w2 : w1;
    uint32_t out = 0;
#pragma unroll
    for (int q = 0; q < 2; q++) {
        int ch = k0 + q;
        float v = w[n * 576 + ch * 9 + t];
        __nv_bfloat16 hi = __float2bfloat16(v);
        __nv_bfloat16 bf = sb ? __float2bfloat16(v - __bfloat162float(hi)) : hi;
        out |= ((uint32_t)__bfloat16_as_ushort(bf)) << (16 * q);
    }
    g_Wfrag[idx] = out;
}

// ---------------- record store with reflect mirrors --------------------------
__device__ __forceinline__ void store_rec_mirror(uint4* base, int row0, int col0,
                                                 int row1, int col1,
                                                 const uint4* rec) {
    int rows[2] = { row0, row1 };
    int cols[2] = { col0, col1 };
    int nr = (row1 >= 0) ? 2 : 1;
    int nc = (col1 >= 0) ? 2 : 1;
    for (int r = 0; r < nr; r++)
        for (int c = 0; c < nc; c++) {
            uint4* d = base + ((size_t)rows[r] * PADW + cols[c]) * 16;
#pragma unroll
            for (int j = 0; j < 16; j++) d[j] = rec[j];
        }
}

// ---------------- input prepass: fp32 NCHW -> padded ch-last bf16 hi/lo ------
__global__ __launch_bounds__(256)
void pad_input_kernel(const float* __restrict__ x) {
    const int y = blockIdx.x, b = blockIdx.y, px = threadIdx.x;
    float v[64];
#pragma unroll
    for (int c = 0; c < 64; c++)
        v[c] = x[(((size_t)(b * 64 + c)) << 16) + y * 256 + px];
    uint4 rec[16];
#pragma unroll
    for (int j = 0; j < 16; j++) {
        int k0 = (j & 7) * 8;
        bool lo = j >= 8;
        uint32_t* wp = (uint32_t*)&rec[j];
#pragma unroll
        for (int q = 0; q < 4; q++) {
            float f0 = v[k0 + 2 * q], f1 = v[k0 + 2 * q + 1];
            if (lo) {
                f0 -= __bfloat162float(__float2bfloat16(f0));
                f1 -= __bfloat162float(__float2bfloat16(f1));
            }
            wp[q] = pack2bf(f0, f1);
        }
    }
    uint4* base = (uint4*)(g_padx + (size_t)b * PADW * PADW * 128);
    int rmir = (y == 1) ? 0 : (y == 254 ? 257 : -1);
    int cmir = (px == 1) ? 0 : (px == 254 ? 257 : -1);
    store_rec_mirror(base, y + 1, px + 1, rmir, cmir, rec);
}

// ---------------- conv: mma.sync + frag-LDG weights, M=256/CTA, pipelined ----
#define STRIP_B 66048                 // 258 records x 256B (== st: 64*258*4)
#define CONV_SMEM (2 * STRIP_B)       // 132096 -> 1 CTA/SM

template <bool IS_CONV2>
__global__ __launch_bounds__(256, 1)
void conv_frag_kernel(const __nv_bfloat16* __restrict__ pad,
                      const uint32_t* __restrict__ wfrag,
                      const float* __restrict__ bias,
                      const float* __restrict__ prelu_a,
                      __nv_bfloat16* __restrict__ outp)
{
    extern __shared__ char smem[];
    float* st = (float*)smem;
    __shared__ float s_b[64], s_a[64];

    const int tid = threadIdx.x, lane = tid & 31, wid = tid >> 5;
    const int wm = wid & 3, wn = wid >> 2;
    const int y0 = blockIdx.x, b = blockIdx.y;
    const uint32_t su = s2u(smem);

    if (tid < 64) { s_b[tid] = bias[tid]; s_a[tid] = IS_CONV2 ? 0.f : prelu_a[tid]; }

    float acc[4][4][4];
#pragma unroll
    for (int f = 0; f < 4; f++)
#pragma unroll
        for (int g = 0; g < 4; g++)
#pragma unroll
            for (int c = 0; c < 4; c++) acc[f][g][c] = 0.0f;

    const int mrow = wm * 64 + (lane & 15);
    const int asel = lane >> 4;
    const uint4* wf4 = (const uint4*)wfrag;

    auto stage = [&](int ky, int buf) {
        const char* src = (const char*)(pad +
            (((size_t)b * PADW + (y0 + ky)) * PADW) * 128);
        const uint32_t du = su + buf * STRIP_B;
        for (int i = tid; i < 4128; i += 256) {
            int p = i >> 4, j = i & 15;
            cp16(du + p * 256 + ((j ^ (p & 7)) << 4), src + (size_t)i * 16);
        }
        CP_COMMIT();
    };

    stage(0, 0);
    stage(1, 1);

#pragma unroll
    for (int ky = 0; ky < 3; ky++) {
        if (ky < 2) CP_WAIT1(); else CP_WAIT0();
        __syncthreads();
        const uint32_t sb_u = su + (ky & 1) * STRIP_B;
#pragma unroll
        for (int kx = 0; kx < 3; kx++) {
            const uint4* wb = wf4 + ((size_t)((ky * 3 + kx) * 2 + wn) * 16) * 32 + lane;
#pragma unroll
            for (int ks = 0; ks < 4; ks++) {
                uint32_t ah[4][4], al[4][4];
#pragma unroll
                for (int f = 0; f < 4; f++) {
                    int row = kx + mrow + f * 16;
                    uint32_t base = sb_u + row * 256;
                    int chi = ks * 2 + asel;
                    ldsm_x4(base + (((chi    ) ^ (row & 7)) << 4),
                            ah[f][0], ah[f][1], ah[f][2], ah[f][3]);
                    ldsm_x4(base + (((chi + 8) ^ (row & 7)) << 4),
                            al[f][0], al[f][1], al[f][2], al[f][3]);
                }
#pragma unroll
                for (int h = 0; h < 2; h++) {
                    uint4 BH = wb[((0 * 4 + ks) * 2 + h) * 32];
                    uint4 BL = wb[((1 * 4 + ks) * 2 + h) * 32];
                    uint32_t bh[4] = { BH.x, BH.y, BH.z, BH.w };
                    uint32_t bl[4] = { BL.x, BL.y, BL.z, BL.w };
#pragma unroll
                    for (int gg = 0; gg < 2; gg++) {
                        int g = 2 * h + gg;
#pragma unroll
                        for (int f = 0; f < 4; f++) {
                            mma16816(acc[f][g], ah[f], bh[2 * gg], bh[2 * gg + 1]);
                            mma16816(acc[f][g], al[f], bh[2 * gg], bh[2 * gg + 1]);
                            mma16816(acc[f][g], ah[f], bl[2 * gg], bl[2 * gg + 1]);
                        }
                    }
                }
            }
        }
        if (ky == 0) {          // buf0 fully consumed -> prefetch row 2 into it
            __syncthreads();
            stage(2, 0);
        }
    }

    // ---- epilogue: transpose via st (reuses buffer 0), emit ch-last records --
    __syncthreads();
#pragma unroll
    for (int f = 0; f < 4; f++)
#pragma unroll
        for (int g = 0; g < 4; g++)
#pragma unroll
            for (int c = 0; c < 4; c++) {
                int m = wm * 64 + f * 16 + (lane >> 2) + ((c >> 1) << 3);
                int n = wn * 32 + g * 8 + ((lane & 3) << 1) + (c & 1);
                st[n * 258 + m] = acc[f][g][c] + s_b[n];
            }
    __syncthreads();

    {
        float v[64];
#pragma unroll
        for (int c = 0; c < 64; c++) v[c] = st[c * 258 + tid];

        if (!IS_CONV2) {
#pragma unroll
            for (int c = 0; c < 64; c++) v[c] = v[c] > 0.f ? v[c] : s_a[c] * v[c];
        } else {
            float sum = 0.f, mx = -FLT_MAX;
#pragma unroll
            for (int c = 0; c < 64; c++) { sum += v[c]; mx = fmaxf(mx, v[c]); }
            const int gp = y0 * 256 + tid;
            g_avg[b * HWN + gp] = sum * (1.0f / CH);
            g_max[b * HWN + gp] = mx;
        }

        uint4 rec[16];
#pragma unroll
        for (int j = 0; j < 16; j++) {
            int k0 = (j & 7) * 8;
            bool lo = j >= 8;
            uint32_t* wp = (uint32_t*)&rec[j];
#pragma unroll
            for (int q = 0; q < 4; q++) {
                float f0 = v[k0 + 2 * q], f1 = v[k0 + 2 * q + 1];
                if (lo) {
                    f0 -= __bfloat162float(__float2bfloat16(f0));
                    f1 -= __bfloat162float(__float2bfloat16(f1));
                }
                wp[q] = pack2bf(f0, f1);
            }
        }

        if (!IS_CONV2) {
            uint4* base = (uint4*)(outp + (size_t)b * PADW * PADW * 128);
            int rmir = (y0 == 1) ? 0 : (y0 == 254 ? 257 : -1);
            int cmir = (tid == 1) ? 0 : (tid == 254 ? 257 : -1);
            store_rec_mirror(base, y0 + 1, tid + 1, rmir, cmir, rec);
        } else {
            uint4* dst = (uint4*)(outp + (((size_t)b << 16) + y0 * 256 + tid) * 128);
#pragma unroll
            for (int j = 0; j < 16; j++) dst[j] = rec[j];
        }
    }

    if (IS_CONV2 && tid < 64) {
        float s = 0.0f;
#pragma unroll 8
        for (int p = 0; p < 256; p++) s += st[tid * 258 + p];
        atomicAdd(&g_chansum[b * CH + tid], s);
    }
}

// ---------------- spatial attention conv -------------------------------------
__global__ __launch_bounds__(256)
void sa_kernel(const float* __restrict__ sa_w, const float* __restrict__ sa_b)
{
    int p = blockIdx.x * 256 + threadIdx.x;
    int b = blockIdx.y;
    int x = p & (IMG_W - 1);
    int y = p >> 8;
    float s = sa_b[0];
#pragma unroll
    for (int ky = 0; ky < 3; ky++) {
        int gy = reflect(y + ky - 1, IMG_H);
#pragma unroll
        for (int kx = 0; kx < 3; kx++) {
            int gx = reflect(x + kx - 1, IMG_W);
            int q = b * HWN + gy * IMG_W + gx;
            s = fmaf(sa_w[ky * 3 + kx],     g_avg[q], s);
            s = fmaf(sa_w[9 + ky * 3 + kx], g_max[q], s);
        }
    }
    g_sg[b * HWN + p] = 1.0f / (1.0f + expf(-s));
}

// ---------------- per-batch small dense math + K prepack ---------------------
__global__ __launch_bounds__(256)
void small_kernel(const float* __restrict__ h_in,
                  const float* __restrict__ ca_w1, const float* __restrict__ ca_b1,
                  const float* __restrict__ ca_a,
                  const float* __restrict__ ca_w2, const float* __restrict__ ca_b2,
                  const float* __restrict__ fc_w,  const float* __restrict__ fc_b,
                  const float* __restrict__ k1_w,  const float* __restrict__ k1_b,
                  const float* __restrict__ k2_w,  const float* __restrict__ k2_b,
                  const float* __restrict__ k3_w,  const float* __restrict__ k3_b)
{
    __shared__ float g[64], t1[32], cv[64], hv[16], t0[16], ta[32], tb[32];
    const int b = blockIdx.x;
    const int tid = threadIdx.x;

    if (tid < 64) g[tid] = g_chansum[b * CH + tid] * (1.0f / HWN);
    if (tid < 16) hv[tid] = h_in[b * 16 + tid];
    __syncthreads();

    if (tid < 32) {
        float s = ca_b1[tid];
        for (int c = 0; c < 64; c++) s = fmaf(ca_w1[tid * 64 + c], g[c], s);
        t1[tid] = s > 0.0f ? s : ca_a[tid] * s;
    }
    if (tid >= 32 && tid < 48) {
        int j = tid - 32;
        float s = fc_b[j];
        for (int c = 0; c < 16; c++) s = fmaf(fc_w[j * 16 + c], hv[c], s);
        t0[j] = s >= 0.0f ? s : 0.01f * s;
    }
    __syncthreads();

    if (tid < 64) {
        float s = ca_b2[tid];
        for (int j = 0; j < 32; j++) s = fmaf(ca_w2[tid * 32 + j], t1[j], s);
        cv[tid] = 1.0f / (1.0f + expf(-s));
    }
    if (tid >= 64 && tid < 96) {
        int j = tid - 64;
        float s = k1_b[j];
        for (int c = 0; c < 16; c++) s = fmaf(k1_w[j * 16 + c], t0[c], s);
        ta[j] = s >= 0.0f ? s : 0.01f * s;
    }
    __syncthreads();

    if (tid < 32) {
        float s = k2_b[tid];
        for (int j = 0; j < 32; j++) s = fmaf(k2_w[tid * 32 + j], ta[j], s);
        tb[tid] = s >= 0.0f ? s : 0.01f * s;
    }
    __syncthreads();

    for (int idx = tid; idx < 8192; idx += 256) {
        float s = k3_b[idx];
        for (int j = 0; j < 32; j++) s = fmaf(k3_w[idx * 32 + j], tb[j], s);
        int o = idx >> 7, i = idx & 127;
        int which = (i >= 64);
        int ch = i & 63;
        float val = which ? s * cv[ch] : s;
        __nv_bfloat16 hi = __float2bfloat16(val);
        __nv_bfloat16 lo = __float2bfloat16(val - __bfloat162float(hi));
        size_t base = (size_t)b * 16384 + (which * 64 + o) * 128 + ch;
        g_Kpk[base]      = hi;
        g_Kpk[base + 64] = lo;
    }
}

// ---------------- final: tensor-core dual matvec + residual ------------------
#define PF  136
#define STP 132
#define KM_B   34816
#define SLR_B  32768
#define FIN_SMEM (KM_B + SLR_B + 512)   // 68096

__global__ __launch_bounds__(256)
void final_kernel(const float* __restrict__ hc_bias,
                  const float* __restrict__ x,
                  float* __restrict__ out)
{
    extern __shared__ char smem[];
    __nv_bfloat16* sKm = (__nv_bfloat16*)smem;       // [128 rows][PF]
    char* slabR = smem + KM_B;                       // 128 records x 256B, swizzled
    float* ssg = (float*)(smem + KM_B + SLR_B);      // [128]
    float* st  = (float*)smem;                       // epilogue reuse
    __shared__ float sbias[64];

    const int tid  = threadIdx.x;
    const int lane = tid & 31;
    const int wid  = tid >> 5;
    const int wm   = wid & 3;
    const int wn   = wid >> 2;
    const int b    = blockIdx.y;
    const int p0   = blockIdx.x * 128;
    const uint32_t sr_u = s2u(slabR);

    if (tid < 64) sbias[tid] = hc_bias[tid];
    const __nv_bfloat16* ksrc = g_Kpk + (size_t)b * 16384;
    for (int idx = tid; idx < 2048; idx += 256) {
        int r = idx >> 4, v = (idx & 15) << 3;
        *(uint4*)(sKm + r * PF + v) = *(const uint4*)(ksrc + r * 128 + v);
    }
    {
        const char* src = (const char*)(g_rcl + (((size_t)b << 16) + p0) * 128);
        for (int i = tid; i < 2048; i += 256) {
            int p = i >> 4, j = i & 15;
            cp16(sr_u + p * 256 + ((j ^ (p & 7)) << 4), src + (size_t)i * 16);
        }
        CP_COMMIT();
    }
    if (tid < 128) ssg[tid] = g_sg[b * HWN + p0 + tid];
    CP_WAIT0();
    __syncthreads();

    const uint32_t km_u = s2u(sKm);
    const int mrow = wm * 32 + (lane & 15);
    const int asel = lane >> 4;
    const int bg    = lane >> 4;
    const int bk    = ((lane >> 3) & 1) << 3;
    const int blrow = lane & 7;

    float acc[2][2][4][4];
#pragma unroll
    for (int s = 0; s < 2; s++)
#pragma unroll
        for (int f = 0; f < 2; f++)
#pragma unroll
            for (int g = 0; g < 4; g++)
#pragma unroll
                for (int c = 0; c < 4; c++) acc[s][f][g][c] = 0.0f;

#pragma unroll
    for (int ks = 0; ks < 4; ks++) {
        uint32_t ah[2][4], al[2][4];
#pragma unroll
        for (int f = 0; f < 2; f++) {
            int row = mrow + f * 16;
            uint32_t base = sr_u + row * 256;
            int chi = ks * 2 + asel;
            ldsm_x4(base + (((chi    ) ^ (row & 7)) << 4),
                    ah[f][0], ah[f][1], ah[f][2], ah[f][3]);
            ldsm_x4(base + (((chi + 8) ^ (row & 7)) << 4),
                    al[f][0], al[f][1], al[f][2], al[f][3]);
        }
#pragma unroll
        for (int s = 0; s < 2; s++) {
#pragma unroll
            for (int gp = 0; gp < 2; gp++) {
                int brow = s * 64 + wn * 32 + (2 * gp + bg) * 8 + blrow;
                uint32_t bb = km_u + (uint32_t)((brow * PF + bk + ks * 16) * 2);
                uint32_t bh0, bh1, bh2, bh3, bl0, bl1, bl2, bl3;
                ldsm_x4(bb,       bh0, bh1, bh2, bh3);
                ldsm_x4(bb + 128, bl0, bl1, bl2, bl3);
#pragma unroll
                for (int f = 0; f < 2; f++) {
                    mma16816(acc[s][f][2 * gp],     ah[f], bh0, bh1);
                    mma16816(acc[s][f][2 * gp],     al[f], bh0, bh1);
                    mma16816(acc[s][f][2 * gp],     ah[f], bl0, bl1);
                    mma16816(acc[s][f][2 * gp + 1], ah[f], bh2, bh3);
                    mma16816(acc[s][f][2 * gp + 1], al[f], bh2, bh3);
                    mma16816(acc[s][f][2 * gp + 1], ah[f], bl2, bl3);
                }
            }
        }
    }

    __syncthreads();
#pragma unroll
    for (int f = 0; f < 2; f++)
#pragma unroll
        for (int g = 0; g < 4; g++)
#pragma unroll
            for (int c = 0; c < 4; c++) {
                int m = wm * 32 + f * 16 + (lane >> 2) + ((c >> 1) << 3);
                int n = wn * 32 + g * 8 + ((lane & 3) << 1) + (c & 1);
                st[n * STP + m] = ssg[m] * acc[0][f][g][c] + acc[1][f][g][c] + sbias[n];
            }
    __syncthreads();

    const size_t obase = (size_t)b * CH * HWN + p0;
    for (int idx = tid; idx < 2048; idx += 256) {
        int oc = idx >> 5, v = (idx & 31) << 2;
        size_t gi = obase + (size_t)oc * HWN + v;
        float4 xv = *(const float4*)&x[gi];
        float4 sv = *(const float4*)&st[oc * STP + v];
        float4 ov = { xv.x + sv.x, xv.y + sv.y, xv.z + sv.z, xv.w + sv.w };
        *(float4*)&out[gi] = ov;
    }
}

// ---------------- launch ----------------------------------------------------
extern "C" void kernel_launch(void* const* d_in, const int* in_sizes, int n_in,
                              void* d_out, int out_size)
{
    const float* x       = (const float*)d_in[0];
    const float* h       = (const float*)d_in[1];
    const float* conv1_w = (const float*)d_in[2];
    const float* conv1_b = (const float*)d_in[3];
    const float* prelu_a = (const float*)d_in[4];
    const float* conv2_w = (const float*)d_in[5];
    const float* conv2_b = (const float*)d_in[6];
    const float* sa_w    = (const float*)d_in[7];
    const float* sa_b    = (const float*)d_in[8];
    const float* ca_w1   = (const float*)d_in[9];
    const float* ca_b1   = (const float*)d_in[10];
    const float* ca_a    = (const float*)d_in[11];
    const float* ca_w2   = (const float*)d_in[12];
    const float* ca_b2   = (const float*)d_in[13];
    const float* fc_w    = (const float*)d_in[14];
    const float* fc_b    = (const float*)d_in[15];
    const float* k1_w    = (const float*)d_in[16];
    const float* k1_b    = (const float*)d_in[17];
    const float* k2_w    = (const float*)d_in[18];
    const float* k2_b    = (const float*)d_in[19];
    const float* k3_w    = (const float*)d_in[20];
    const float* k3_b    = (const float*)d_in[21];
    const float* hc_bias = (const float*)d_in[22];
    float* out = (float*)d_out;

    __nv_bfloat16 *padx = nullptr, *pad1 = nullptr, *rcl = nullptr;
    uint32_t* wfr = nullptr;
    cudaGetSymbolAddress((void**)&padx, g_padx);
    cudaGetSymbolAddress((void**)&pad1, g_pad1);
    cudaGetSymbolAddress((void**)&rcl,  g_rcl);
    cudaGetSymbolAddress((void**)&wfr,  g_Wfrag);

    static bool attr_set = false;
    if (!attr_set) {
        cudaFuncSetAttribute(conv_frag_kernel<false>,
                             cudaFuncAttributeMaxDynamicSharedMemorySize, CONV_SMEM);
        cudaFuncSetAttribute(conv_frag_kernel<true>,
                             cudaFuncAttributeMaxDynamicSharedMemorySize, CONV_SMEM);
        cudaFuncSetAttribute(final_kernel,
                             cudaFuncAttributeMaxDynamicSharedMemorySize, FIN_SMEM);
        attr_set = true;
    }

    init_kernel<<<2, 256>>>();
    wfrag_kernel<<<288, 256>>>(conv1_w, conv2_w);
    pad_input_kernel<<<dim3(256, NB), 256>>>(x);

    dim3 cgrid(IMG_H, NB);
    conv_frag_kernel<false><<<cgrid, 256, CONV_SMEM>>>(padx, wfr, conv1_b, prelu_a, pad1);
    conv_frag_kernel<true ><<<cgrid, 256, CONV_SMEM>>>(pad1, wfr + 36864, conv2_b, prelu_a, rcl);

    sa_kernel<<<dim3(HWN / 256, NB), 256>>>(sa_w, sa_b);

    small_kernel<<<NB, 256>>>(h, ca_w1, ca_b1, ca_a, ca_w2, ca_b2,
                              fc_w, fc_b, k1_w, k1_b, k2_w, k2_b, k3_w, k3_b);

    final_kernel<<<dim3(HWN / 128, NB), 256, FIN_SMEM>>>(hc_bias, x, out);
}

// round 12
// speedup vs baseline: 1.0631x; 1.0631x over previous
#include <cuda_runtime.h>
#include <cuda_bf16.h>
#include <math.h>
#include <float.h>
#include <stdint.h>

#define CH    64
#define IMG_W 256
#define IMG_H 256
#define HWN   65536
#define NB    8
#define PADW  258

// ---------------- device-global scratch -------------------------------------
__device__ __align__(16) __nv_bfloat16 g_padx[NB * PADW * PADW * 128];
__device__ __align__(16) __nv_bfloat16 g_pad1[NB * PADW * PADW * 128];
__device__ __align__(16) __nv_bfloat16 g_rcl [NB * HWN * 128];
__device__ __align__(16) float g_avg[NB * HWN];
__device__ __align__(16) float g_max[NB * HWN];
__device__ __align__(16) float g_sg [NB * HWN];
__device__ float g_chansum[NB * CH];
__device__ __align__(16) __nv_bfloat16 g_Kpk[NB * 2 * 64 * 128];
__device__ __align__(16) uint32_t g_Wfrag[73728];   // [cv][t][wn][sb][ks][h][lane][e]

// ---------------- helpers ----------------------------------------------------
__device__ __forceinline__ int reflect(int v, int n) {
    if (v < 0) v = -v;
    if (v >= n) v = 2 * n - 2 - v;
    return v;
}
__device__ __forceinline__ uint32_t s2u(const void* p) {
    return (uint32_t)__cvta_generic_to_shared(p);
}
__device__ __forceinline__ uint32_t pack2bf(float a, float b) {
    return ((uint32_t)__bfloat16_as_ushort(__float2bfloat16(a))) |
           ((uint32_t)__bfloat16_as_ushort(__float2bfloat16(b)) << 16);
}
__device__ __forceinline__ void ldsm_x4(uint32_t addr, uint32_t& r0, uint32_t& r1,
                                        uint32_t& r2, uint32_t& r3) {
    asm volatile("ldmatrix.sync.aligned.m8n8.x4.shared.b16 {%0,%1,%2,%3}, [%4];"
                 : "=r"(r0), "=r"(r1), "=r"(r2), "=r"(r3) : "r"(addr));
}
__device__ __forceinline__ void mma16816(float* c, const uint32_t* a,
                                         uint32_t b0, uint32_t b1) {
    asm volatile("mma.sync.aligned.m16n8k16.row.col.f32.bf16.bf16.f32 "
                 "{%0,%1,%2,%3}, {%4,%5,%6,%7}, {%8,%9}, {%0,%1,%2,%3};"
                 : "+f"(c[0]), "+f"(c[1]), "+f"(c[2]), "+f"(c[3])
                 : "r"(a[0]), "r"(a[1]), "r"(a[2]), "r"(a[3]), "r"(b0), "r"(b1));
}
__device__ __forceinline__ void cp16(uint32_t dst, const void* src) {
    asm volatile("cp.async.ca.shared.global [%0], [%1], 16;" :: "r"(dst), "l"(src));
}
#define CP_COMMIT() asm volatile("cp.async.commit_group;" ::: "memory")
#define CP_WAIT0()  asm volatile("cp.async.wait_group 0;" ::: "memory")
#define PAIRBAR(wm) asm volatile("bar.sync %0, 64;" :: "r"(1 + (wm)) : "memory")

// ---------------- init ----------------
__global__ void init_kernel() {
    int i = blockIdx.x * blockDim.x + threadIdx.x;
    if (i < NB * CH) g_chansum[i] = 0.0f;
}

// ---------------- weight frag prepack (lane-fastest, coalesced) --------------
__global__ __launch_bounds__(256)
void wfrag_kernel(const float* __restrict__ w1, const float* __restrict__ w2) {
    int idx = blockIdx.x * 256 + threadIdx.x;
    if (idx >= 73728) return;
    int e    = idx & 3;
    int lane = (idx >> 2) & 31;
    int h    = (idx >> 7) & 1;
    int ks   = (idx >> 8) & 3;
    int sb   = (idx >> 10) & 1;
    int wn   = (idx >> 11) & 1;
    int rest = idx >> 12;
    int t    = rest % 9;
    int cv   = rest / 9;
    int nt = 2 * h + (e >> 1);
    int rr = e & 1;
    int n  = wn * 32 + nt * 8 + (lane >> 2);
    int k0 = ks * 16 + rr * 8 + (lane & 3) * 2;
    const float* w = cv ? w2 : w1;
    uint32_t out = 0;
#pragma unroll
    for (int q = 0; q < 2; q++) {
        int ch = k0 + q;
        float v = w[n * 576 + ch * 9 + t];
        __nv_bfloat16 hi = __float2bfloat16(v);
        __nv_bfloat16 bf = sb ? __float2bfloat16(v - __bfloat162float(hi)) : hi;
        out |= ((uint32_t)__bfloat16_as_ushort(bf)) << (16 * q);
    }
    g_Wfrag[idx] = out;
}

// ---------------- record store with reflect mirrors --------------------------
__device__ __forceinline__ void store_rec_mirror(uint4* base, int row0, int col0,
                                                 int row1, int col1,
                                                 const uint4* rec) {
    int rows[2] = { row0, row1 };
    int cols[2] = { col0, col1 };
    int nr = (row1 >= 0) ? 2 : 1;
    int nc = (col1 >= 0) ? 2 : 1;
    for (int r = 0; r < nr; r++)
        for (int c = 0; c < nc; c++) {
            uint4* d = base + ((size_t)rows[r] * PADW + cols[c]) * 16;
#pragma unroll
            for (int j = 0; j < 16; j++) d[j] = rec[j];
        }
}

// ---------------- input prepass: fp32 NCHW -> padded ch-last bf16 hi/lo ------
__global__ __launch_bounds__(256)
void pad_input_kernel(const float* __restrict__ x) {
    const int y = blockIdx.x, b = blockIdx.y, px = threadIdx.x;
    float v[64];
#pragma unroll
    for (int c = 0; c < 64; c++)
        v[c] = x[(((size_t)(b * 64 + c)) << 16) + y * 256 + px];
    uint4 rec[16];
#pragma unroll
    for (int j = 0; j < 16; j++) {
        int k0 = (j & 7) * 8;
        bool lo = j >= 8;
        uint32_t* wp = (uint32_t*)&rec[j];
#pragma unroll
        for (int q = 0; q < 4; q++) {
            float f0 = v[k0 + 2 * q], f1 = v[k0 + 2 * q + 1];
            if (lo) {
                f0 -= __bfloat162float(__float2bfloat16(f0));
                f1 -= __bfloat162float(__float2bfloat16(f1));
            }
            wp[q] = pack2bf(f0, f1);
        }
    }
    uint4* base = (uint4*)(g_padx + (size_t)b * PADW * PADW * 128);
    int rmir = (y == 1) ? 0 : (y == 254 ? 257 : -1);
    int cmir = (px == 1) ? 0 : (px == 254 ? 257 : -1);
    store_rec_mirror(base, y + 1, px + 1, rmir, cmir, rec);
}

// ---------------- conv: mma.sync + frag-LDG weights, M=256/CTA ---------------
// Per-pair private strips: pair wm owns 66 records (rows wm*64 .. wm*64+65),
// staged by its own 2 warps, synced with named barriers only.
#define PAIR_B 16896                  // 66 records x 256B
#define CONV_SMEM (4 * PAIR_B)        // 67584 (st epilogue 66048 fits)

template <bool IS_CONV2>
__global__ __launch_bounds__(256, 2)
void conv_frag_kernel(const __nv_bfloat16* __restrict__ pad,
                      const uint32_t* __restrict__ wfrag,
                      const float* __restrict__ bias,
                      const float* __restrict__ prelu_a,
                      __nv_bfloat16* __restrict__ outp)
{
    extern __shared__ char smem[];
    float* st = (float*)smem;
    __shared__ float s_b[64], s_a[64];

    const int tid = threadIdx.x, lane = tid & 31, wid = tid >> 5;
    const int wm = wid & 3, wn = wid >> 2;
    const int y0 = blockIdx.x, b = blockIdx.y;
    const uint32_t su = s2u(smem);
    const uint32_t pu = su + wm * PAIR_B;        // this pair's strip
    const int pair_tid = wn * 32 + lane;         // 0..63 within pair

    if (tid < 64) { s_b[tid] = bias[tid]; s_a[tid] = IS_CONV2 ? 0.f : prelu_a[tid]; }

    float acc[4][4][4];
#pragma unroll
    for (int f = 0; f < 4; f++)
#pragma unroll
        for (int g = 0; g < 4; g++)
#pragma unroll
            for (int c = 0; c < 4; c++) acc[f][g][c] = 0.0f;

    const int mlocal = lane & 15;                // local row within pair strip
    const int asel = lane >> 4;
    const uint4* wf4 = (const uint4*)wfrag;

#pragma unroll
    for (int ky = 0; ky < 3; ky++) {
        if (ky) PAIRBAR(wm);                     // pair done reading prev row
        {
            // stage this pair's 66 records of row (y0+ky): global recs wm*64..+65
            const char* src = (const char*)(pad +
                (((size_t)b * PADW + (y0 + ky)) * PADW + wm * 64) * 128);
            for (int i = pair_tid; i < 1056; i += 64) {
                int p = i >> 4, j = i & 15;
                cp16(pu + p * 256 + ((j ^ (p & 7)) << 4),
                     src + (size_t)p * 256 + j * 16);
            }
            CP_COMMIT(); CP_WAIT0();
        }
        PAIRBAR(wm);                             // both halves visible to pair
#pragma unroll
        for (int kx = 0; kx < 3; kx++) {
            const uint4* wb = wf4 + ((size_t)((ky * 3 + kx) * 2 + wn) * 16) * 32 + lane;
#pragma unroll
            for (int ks = 0; ks < 4; ks++) {
                uint32_t ah[4][4], al[4][4];
#pragma unroll
                for (int f = 0; f < 4; f++) {
                    int row = kx + mlocal + f * 16;          // local row 0..65
                    uint32_t base = pu + row * 256;
                    int chi = ks * 2 + asel;
                    ldsm_x4(base + (((chi    ) ^ (row & 7)) << 4),
                            ah[f][0], ah[f][1], ah[f][2], ah[f][3]);
                    ldsm_x4(base + (((chi + 8) ^ (row & 7)) << 4),
                            al[f][0], al[f][1], al[f][2], al[f][3]);
                }
#pragma unroll
                for (int h = 0; h < 2; h++) {
                    uint4 BH = wb[((0 * 4 + ks) * 2 + h) * 32];
                    uint4 BL = wb[((1 * 4 + ks) * 2 + h) * 32];
                    uint32_t bh[4] = { BH.x, BH.y, BH.z, BH.w };
                    uint32_t bl[4] = { BL.x, BL.y, BL.z, BL.w };
#pragma unroll
                    for (int gg = 0; gg < 2; gg++) {
                        int g = 2 * h + gg;
#pragma unroll
                        for (int f = 0; f < 4; f++) {
                            mma16816(acc[f][g], ah[f], bh[2 * gg], bh[2 * gg + 1]);
                            mma16816(acc[f][g], al[f], bh[2 * gg], bh[2 * gg + 1]);
                            mma16816(acc[f][g], ah[f], bl[2 * gg], bl[2 * gg + 1]);
                        }
                    }
                }
            }
        }
    }

    // ---- epilogue: transpose via st (reuses strips), emit ch-last records ----
    __syncthreads();
#pragma unroll
    for (int f = 0; f < 4; f++)
#pragma unroll
        for (int g = 0; g < 4; g++)
#pragma unroll
            for (int c = 0; c < 4; c++) {
                int m = wm * 64 + f * 16 + (lane >> 2) + ((c >> 1) << 3);
                int n = wn * 32 + g * 8 + ((lane & 3) << 1) + (c & 1);
                st[n * 258 + m] = acc[f][g][c] + s_b[n];
            }
    __syncthreads();

    {
        float v[64];
#pragma unroll
        for (int c = 0; c < 64; c++) v[c] = st[c * 258 + tid];

        if (!IS_CONV2) {
#pragma unroll
            for (int c = 0; c < 64; c++) v[c] = v[c] > 0.f ? v[c] : s_a[c] * v[c];
        } else {
            float sum = 0.f, mx = -FLT_MAX;
#pragma unroll
            for (int c = 0; c < 64; c++) { sum += v[c]; mx = fmaxf(mx, v[c]); }
            const int gp = y0 * 256 + tid;
            g_avg[b * HWN + gp] = sum * (1.0f / CH);
            g_max[b * HWN + gp] = mx;
        }

        uint4 rec[16];
#pragma unroll
        for (int j = 0; j < 16; j++) {
            int k0 = (j & 7) * 8;
            bool lo = j >= 8;
            uint32_t* wp = (uint32_t*)&rec[j];
#pragma unroll
            for (int q = 0; q < 4; q++) {
                float f0 = v[k0 + 2 * q], f1 = v[k0 + 2 * q + 1];
                if (lo) {
                    f0 -= __bfloat162float(__float2bfloat16(f0));
                    f1 -= __bfloat162float(__float2bfloat16(f1));
                }
                wp[q] = pack2bf(f0, f1);
            }
        }

        if (!IS_CONV2) {
            uint4* base = (uint4*)(outp + (size_t)b * PADW * PADW * 128);
            int rmir = (y0 == 1) ? 0 : (y0 == 254 ? 257 : -1);
            int cmir = (tid == 1) ? 0 : (tid == 254 ? 257 : -1);
            store_rec_mirror(base, y0 + 1, tid + 1, rmir, cmir, rec);
        } else {
            uint4* dst = (uint4*)(outp + (((size_t)b << 16) + y0 * 256 + tid) * 128);
#pragma unroll
            for (int j = 0; j < 16; j++) dst[j] = rec[j];
        }
    }

    if (IS_CONV2) {
        // parallel chansum: 4 threads per oc
        int oc = tid >> 2;
        float s = 0.0f;
        for (int p = (tid & 3); p < 256; p += 4) s += st[oc * 258 + p];
        s += __shfl_xor_sync(0xFFFFFFFFu, s, 1);
        s += __shfl_xor_sync(0xFFFFFFFFu, s, 2);
        if ((tid & 3) == 0) atomicAdd(&g_chansum[b * CH + oc], s);
    }
}

// ---------------- spatial attention conv -------------------------------------
__global__ __launch_bounds__(256)
void sa_kernel(const float* __restrict__ sa_w, const float* __restrict__ sa_b)
{
    int p = blockIdx.x * 256 + threadIdx.x;
    int b = blockIdx.y;
    int x = p & (IMG_W - 1);
    int y = p >> 8;
    float s = sa_b[0];
#pragma unroll
    for (int ky = 0; ky < 3; ky++) {
        int gy = reflect(y + ky - 1, IMG_H);
#pragma unroll
        for (int kx = 0; kx < 3; kx++) {
            int gx = reflect(x + kx - 1, IMG_W);
            int q = b * HWN + gy * IMG_W + gx;
            s = fmaf(sa_w[ky * 3 + kx],     g_avg[q], s);
            s = fmaf(sa_w[9 + ky * 3 + kx], g_max[q], s);
        }
    }
    g_sg[b * HWN + p] = 1.0f / (1.0f + expf(-s));
}

// ---------------- per-batch small dense math + K prepack ---------------------
__global__ __launch_bounds__(256)
void small_kernel(const float* __restrict__ h_in,
                  const float* __restrict__ ca_w1, const float* __restrict__ ca_b1,
                  const float* __restrict__ ca_a,
                  const float* __restrict__ ca_w2, const float* __restrict__ ca_b2,
                  const float* __restrict__ fc_w,  const float* __restrict__ fc_b,
                  const float* __restrict__ k1_w,  const float* __restrict__ k1_b,
                  const float* __restrict__ k2_w,  const float* __restrict__ k2_b,
                  const float* __restrict__ k3_w,  const float* __restrict__ k3_b)
{
    __shared__ float g[64], t1[32], cv[64], hv[16], t0[16], ta[32], tb[32];
    const int b = blockIdx.x;
    const int tid = threadIdx.x;

    if (tid < 64) g[tid] = g_chansum[b * CH + tid] * (1.0f / HWN);
    if (tid < 16) hv[tid] = h_in[b * 16 + tid];
    __syncthreads();

    if (tid < 32) {
        float s = ca_b1[tid];
        for (int c = 0; c < 64; c++) s = fmaf(ca_w1[tid * 64 + c], g[c], s);
        t1[tid] = s > 0.0f ? s : ca_a[tid] * s;
    }
    if (tid >= 32 && tid < 48) {
        int j = tid - 32;
        float s = fc_b[j];
        for (int c = 0; c < 16; c++) s = fmaf(fc_w[j * 16 + c], hv[c], s);
        t0[j] = s >= 0.0f ? s : 0.01f * s;
    }
    __syncthreads();

    if (tid < 64) {
        float s = ca_b2[tid];
        for (int j = 0; j < 32; j++) s = fmaf(ca_w2[tid * 32 + j], t1[j], s);
        cv[tid] = 1.0f / (1.0f + expf(-s));
    }
    if (tid >= 64 && tid < 96) {
        int j = tid - 64;
        float s = k1_b[j];
        for (int c = 0; c < 16; c++) s = fmaf(k1_w[j * 16 + c], t0[c], s);
        ta[j] = s >= 0.0f ? s : 0.01f * s;
    }
    __syncthreads();

    if (tid < 32) {
        float s = k2_b[tid];
        for (int j = 0; j < 32; j++) s = fmaf(k2_w[tid * 32 + j], ta[j], s);
        tb[tid] = s >= 0.0f ? s : 0.01f * s;
    }
    __syncthreads();

    for (int idx = tid; idx < 8192; idx += 256) {
        float s = k3_b[idx];
        for (int j = 0; j < 32; j++) s = fmaf(k3_w[idx * 32 + j], tb[j], s);
        int o = idx >> 7, i = idx & 127;
        int which = (i >= 64);
        int ch = i & 63;
        float val = which ? s * cv[ch] : s;
        __nv_bfloat16 hi = __float2bfloat16(val);
        __nv_bfloat16 lo = __float2bfloat16(val - __bfloat162float(hi));
        size_t base = (size_t)b * 16384 + (which * 64 + o) * 128 + ch;
        g_Kpk[base]      = hi;
        g_Kpk[base + 64] = lo;
    }
}

// ---------------- final: tensor-core dual matvec + residual ------------------
#define PF  136
#define STP 132
#define KM_B   34816
#define SLR_B  32768
#define FIN_SMEM (KM_B + SLR_B + 512)   // 68096

__global__ __launch_bounds__(256)
void final_kernel(const float* __restrict__ hc_bias,
                  const float* __restrict__ x,
                  float* __restrict__ out)
{
    extern __shared__ char smem[];
    __nv_bfloat16* sKm = (__nv_bfloat16*)smem;       // [128 rows][PF]
    char* slabR = smem + KM_B;                       // 128 records x 256B, swizzled
    float* ssg = (float*)(smem + KM_B + SLR_B);      // [128]
    float* st  = (float*)smem;                       // epilogue reuse
    __shared__ float sbias[64];

    const int tid  = threadIdx.x;
    const int lane = tid & 31;
    const int wid  = tid >> 5;
    const int wm   = wid & 3;
    const int wn   = wid >> 2;
    const int b    = blockIdx.y;
    const int p0   = blockIdx.x * 128;
    const uint32_t sr_u = s2u(slabR);

    if (tid < 64) sbias[tid] = hc_bias[tid];
    const __nv_bfloat16* ksrc = g_Kpk + (size_t)b * 16384;
    for (int idx = tid; idx < 2048; idx += 256) {
        int r = idx >> 4, v = (idx & 15) << 3;
        *(uint4*)(sKm + r * PF + v) = *(const uint4*)(ksrc + r * 128 + v);
    }
    {
        const char* src = (const char*)(g_rcl + (((size_t)b << 16) + p0) * 128);
        for (int i = tid; i < 2048; i += 256) {
            int p = i >> 4, j = i & 15;
            cp16(sr_u + p * 256 + ((j ^ (p & 7)) << 4), src + (size_t)i * 16);
        }
        CP_COMMIT();
    }
    if (tid < 128) ssg[tid] = g_sg[b * HWN + p0 + tid];
    CP_WAIT0();
    __syncthreads();

    const uint32_t km_u = s2u(sKm);
    const int mrow = wm * 32 + (lane & 15);
    const int asel = lane >> 4;
    const int bg    = lane >> 4;
    const int bk    = ((lane >> 3) & 1) << 3;
    const int blrow = lane & 7;

    float acc[2][2][4][4];
#pragma unroll
    for (int s = 0; s < 2; s++)
#pragma unroll
        for (int f = 0; f < 2; f++)
#pragma unroll
            for (int g = 0; g < 4; g++)
#pragma unroll
                for (int c = 0; c < 4; c++) acc[s][f][g][c] = 0.0f;

#pragma unroll
    for (int ks = 0; ks < 4; ks++) {
        uint32_t ah[2][4], al[2][4];
#pragma unroll
        for (int f = 0; f < 2; f++) {
            int row = mrow + f * 16;
            uint32_t base = sr_u + row * 256;
            int chi = ks * 2 + asel;
            ldsm_x4(base + (((chi    ) ^ (row & 7)) << 4),
                    ah[f][0], ah[f][1], ah[f][2], ah[f][3]);
            ldsm_x4(base + (((chi + 8) ^ (row & 7)) << 4),
                    al[f][0], al[f][1], al[f][2], al[f][3]);
        }
#pragma unroll
        for (int s = 0; s < 2; s++) {
#pragma unroll
            for (int gp = 0; gp < 2; gp++) {
                int brow = s * 64 + wn * 32 + (2 * gp + bg) * 8 + blrow;
                uint32_t bb = km_u + (uint32_t)((brow * PF + bk + ks * 16) * 2);
                uint32_t bh0, bh1, bh2, bh3, bl0, bl1, bl2, bl3;
                ldsm_x4(bb,       bh0, bh1, bh2, bh3);
                ldsm_x4(bb + 128, bl0, bl1, bl2, bl3);
#pragma unroll
                for (int f = 0; f < 2; f++) {
                    mma16816(acc[s][f][2 * gp],     ah[f], bh0, bh1);
                    mma16816(acc[s][f][2 * gp],     al[f], bh0, bh1);
                    mma16816(acc[s][f][2 * gp],     ah[f], bl0, bl1);
                    mma16816(acc[s][f][2 * gp + 1], ah[f], bh2, bh3);
                    mma16816(acc[s][f][2 * gp + 1], al[f], bh2, bh3);
                    mma16816(acc[s][f][2 * gp + 1], ah[f], bl2, bl3);
                }
            }
        }
    }

    __syncthreads();
#pragma unroll
    for (int f = 0; f < 2; f++)
#pragma unroll
        for (int g = 0; g < 4; g++)
#pragma unroll
            for (int c = 0; c < 4; c++) {
                int m = wm * 32 + f * 16 + (lane >> 2) + ((c >> 1) << 3);
                int n = wn * 32 + g * 8 + ((lane & 3) << 1) + (c & 1);
                st[n * STP + m] = ssg[m] * acc[0][f][g][c] + acc[1][f][g][c] + sbias[n];
            }
    __syncthreads();

    const size_t obase = (size_t)b * CH * HWN + p0;
    for (int idx = tid; idx < 2048; idx += 256) {
        int oc = idx >> 5, v = (idx & 31) << 2;
        size_t gi = obase + (size_t)oc * HWN + v;
        float4 xv = *(const float4*)&x[gi];
        float4 sv = *(const float4*)&st[oc * STP + v];
        float4 ov = { xv.x + sv.x, xv.y + sv.y, xv.z + sv.z, xv.w + sv.w };
        *(float4*)&out[gi] = ov;
    }
}

// ---------------- launch ----------------------------------------------------
extern "C" void kernel_launch(void* const* d_in, const int* in_sizes, int n_in,
                              void* d_out, int out_size)
{
    const float* x       = (const float*)d_in[0];
    const float* h       = (const float*)d_in[1];
    const float* conv1_w = (const float*)d_in[2];
    const float* conv1_b = (const float*)d_in[3];
    const float* prelu_a = (const float*)d_in[4];
    const float* conv2_w = (const float*)d_in[5];
    const float* conv2_b = (const float*)d_in[6];
    const float* sa_w    = (const float*)d_in[7];
    const float* sa_b    = (const float*)d_in[8];
    const float* ca_w1   = (const float*)d_in[9];
    const float* ca_b1   = (const float*)d_in[10];
    const float* ca_a    = (const float*)d_in[11];
    const float* ca_w2   = (const float*)d_in[12];
    const float* ca_b2   = (const float*)d_in[13];
    const float* fc_w    = (const float*)d_in[14];
    const float* fc_b    = (const float*)d_in[15];
    const float* k1_w    = (const float*)d_in[16];
    const float* k1_b    = (const float*)d_in[17];
    const float* k2_w    = (const float*)d_in[18];
    const float* k2_b    = (const float*)d_in[19];
    const float* k3_w    = (const float*)d_in[20];
    const float* k3_b    = (const float*)d_in[21];
    const float* hc_bias = (const float*)d_in[22];
    float* out = (float*)d_out;

    __nv_bfloat16 *padx = nullptr, *pad1 = nullptr, *rcl = nullptr;
    uint32_t* wfr = nullptr;
    cudaGetSymbolAddress((void**)&padx, g_padx);
    cudaGetSymbolAddress((void**)&pad1, g_pad1);
    cudaGetSymbolAddress((void**)&rcl,  g_rcl);
    cudaGetSymbolAddress((void**)&wfr,  g_Wfrag);

    static bool attr_set = false;
    if (!attr_set) {
        cudaFuncSetAttribute(conv_frag_kernel<false>,
                             cudaFuncAttributeMaxDynamicSharedMemorySize, CONV_SMEM);
        cudaFuncSetAttribute(conv_frag_kernel<true>,
                             cudaFuncAttributeMaxDynamicSharedMemorySize, CONV_SMEM);
        cudaFuncSetAttribute(final_kernel,
                             cudaFuncAttributeMaxDynamicSharedMemorySize, FIN_SMEM);
        attr_set = true;
    }

    init_kernel<<<2, 256>>>();
    wfrag_kernel<<<288, 256>>>(conv1_w, conv2_w);
    pad_input_kernel<<<dim3(256, NB), 256>>>(x);

    dim3 cgrid(IMG_H, NB);
    conv_frag_kernel<false><<<cgrid, 256, CONV_SMEM>>>(padx, wfr, conv1_b, prelu_a, pad1);
    conv_frag_kernel<true ><<<cgrid, 256, CONV_SMEM>>>(pad1, wfr + 36864, conv2_b, prelu_a, rcl);

    sa_kernel<<<dim3(HWN / 256, NB), 256>>>(sa_w, sa_b);

    small_kernel<<<NB, 256>>>(h, ca_w1, ca_b1, ca_a, ca_w2, ca_b2,
                              fc_w, fc_b, k1_w, k1_b, k2_w, k2_b, k3_w, k3_b);

    final_kernel<<<dim3(HWN / 128, NB), 256, FIN_SMEM>>>(hc_bias, x, out);
}

// round 13
// speedup vs baseline: 1.5276x; 1.4369x over previous
#include <cuda_runtime.h>
#include <cuda_bf16.h>
#include <math.h>
#include <float.h>
#include <stdint.h>

#define CH    64
#define IMG_W 256
#define IMG_H 256
#define HWN   65536
#define NB    8
#define PADW  258

// ---------------- device-global scratch -------------------------------------
__device__ __align__(16) __nv_bfloat16 g_padx[NB * PADW * PADW * 128];
__device__ __align__(16) __nv_bfloat16 g_pad1[NB * PADW * PADW * 128];
__device__ __align__(16) __nv_bfloat16 g_rcl [NB * HWN * 128];
__device__ __align__(16) float g_avg[NB * HWN];
__device__ __align__(16) float g_max[NB * HWN];
__device__ __align__(16) float g_sg [NB * HWN];
__device__ float g_chansum[NB * CH];
__device__ __align__(16) __nv_bfloat16 g_Kpk[NB * 2 * 64 * 128];
__device__ __align__(16) uint32_t g_Wfrag[73728];   // [cv][t][wn][sb][ks][h][lane][e]

// ---------------- helpers ----------------------------------------------------
__device__ __forceinline__ int reflect(int v, int n) {
    if (v < 0) v = -v;
    if (v >= n) v = 2 * n - 2 - v;
    return v;
}
__device__ __forceinline__ uint32_t s2u(const void* p) {
    return (uint32_t)__cvta_generic_to_shared(p);
}
__device__ __forceinline__ uint32_t pack2bf(float a, float b) {
    return ((uint32_t)__bfloat16_as_ushort(__float2bfloat16(a))) |
           ((uint32_t)__bfloat16_as_ushort(__float2bfloat16(b)) << 16);
}
__device__ __forceinline__ void ldsm_x4(uint32_t addr, uint32_t& r0, uint32_t& r1,
                                        uint32_t& r2, uint32_t& r3) {
    asm volatile("ldmatrix.sync.aligned.m8n8.x4.shared.b16 {%0,%1,%2,%3}, [%4];"
                 : "=r"(r0), "=r"(r1), "=r"(r2), "=r"(r3) : "r"(addr));
}
__device__ __forceinline__ void mma16816(float* c, const uint32_t* a,
                                         uint32_t b0, uint32_t b1) {
    asm volatile("mma.sync.aligned.m16n8k16.row.col.f32.bf16.bf16.f32 "
                 "{%0,%1,%2,%3}, {%4,%5,%6,%7}, {%8,%9}, {%0,%1,%2,%3};"
                 : "+f"(c[0]), "+f"(c[1]), "+f"(c[2]), "+f"(c[3])
                 : "r"(a[0]), "r"(a[1]), "r"(a[2]), "r"(a[3]), "r"(b0), "r"(b1));
}
__device__ __forceinline__ void cp16(uint32_t dst, const void* src) {
    asm volatile("cp.async.ca.shared.global [%0], [%1], 16;" :: "r"(dst), "l"(src));
}
#define CP_COMMIT() asm volatile("cp.async.commit_group;" ::: "memory")
#define CP_WAIT0()  asm volatile("cp.async.wait_group 0;" ::: "memory")
#define CP_WAIT1()  asm volatile("cp.async.wait_group 1;" ::: "memory")

// ---------------- init ----------------
__global__ void init_kernel() {
    int i = blockIdx.x * blockDim.x + threadIdx.x;
    if (i < NB * CH) g_chansum[i] = 0.0f;
}

// ---------------- weight frag prepack (lane-fastest, coalesced) --------------
__global__ __launch_bounds__(256)
void wfrag_kernel(const float* __restrict__ w1, const float* __restrict__ w2) {
    int idx = blockIdx.x * 256 + threadIdx.x;
    if (idx >= 73728) return;
    int e    = idx & 3;
    int lane = (idx >> 2) & 31;
    int h    = (idx >> 7) & 1;
    int ks   = (idx >> 8) & 3;
    int sb   = (idx >> 10) & 1;
    int wn   = (idx >> 11) & 1;
    int rest = idx >> 12;
    int t    = rest % 9;
    int cv   = rest / 9;
    int nt = 2 * h + (e >> 1);
    int rr = e & 1;
    int n  = wn * 32 + nt * 8 + (lane >> 2);
    int k0 = ks * 16 + rr * 8 + (lane & 3) * 2;
    const float* w = cv ? w2 : w1;
    uint32_t out = 0;
#pragma unroll
    for (int q = 0; q < 2; q++) {
        int ch = k0 + q;
        float v = w[n * 576 + ch * 9 + t];
        __nv_bfloat16 hi = __float2bfloat16(v);
        __nv_bfloat16 bf = sb ? __float2bfloat16(v - __bfloat162float(hi)) : hi;
        out |= ((uint32_t)__bfloat16_as_ushort(bf)) << (16 * q);
    }
    g_Wfrag[idx] = out;
}

// ---------------- record store with reflect mirrors --------------------------
__device__ __forceinline__ void store_rec_mirror(uint4* base, int row0, int col0,
                                                 int row1, int col1,
                                                 const uint4* rec) {
    int rows[2] = { row0, row1 };
    int cols[2] = { col0, col1 };
    int nr = (row1 >= 0) ? 2 : 1;
    int nc = (col1 >= 0) ? 2 : 1;
    for (int r = 0; r < nr; r++)
        for (int c = 0; c < nc; c++) {
            uint4* d = base + ((size_t)rows[r] * PADW + cols[c]) * 16;
#pragma unroll
            for (int j = 0; j < 16; j++) d[j] = rec[j];
        }
}

// ---------------- input prepass: fp32 NCHW -> padded ch-last bf16 hi/lo ------
__global__ __launch_bounds__(256)
void pad_input_kernel(const float* __restrict__ x) {
    const int y = blockIdx.x, b = blockIdx.y, px = threadIdx.x;
    float v[64];
#pragma unroll
    for (int c = 0; c < 64; c++)
        v[c] = x[(((size_t)(b * 64 + c)) << 16) + y * 256 + px];
    uint4 rec[16];
#pragma unroll
    for (int j = 0; j < 16; j++) {
        int k0 = (j & 7) * 8;
        bool lo = j >= 8;
        uint32_t* wp = (uint32_t*)&rec[j];
#pragma unroll
        for (int q = 0; q < 4; q++) {
            float f0 = v[k0 + 2 * q], f1 = v[k0 + 2 * q + 1];
            if (lo) {
                f0 -= __bfloat162float(__float2bfloat16(f0));
                f1 -= __bfloat162float(__float2bfloat16(f1));
            }
            wp[q] = pack2bf(f0, f1);
        }
    }
    uint4* base = (uint4*)(g_padx + (size_t)b * PADW * PADW * 128);
    int rmir = (y == 1) ? 0 : (y == 254 ? 257 : -1);
    int cmir = (px == 1) ? 0 : (px == 254 ? 257 : -1);
    store_rec_mirror(base, y + 1, px + 1, rmir, cmir, rec);
}

// ---------------- conv: mma.sync + frag-LDG weights, M=256/CTA ---------------
// K split into 2x32-ch chunks -> 33KB half-strips, double-buffered in the same
// 66KB footprint as R9 (2 CTAs/SM preserved). 6-stage cp.async pipeline.
#define HSTRIP_B 33024                // 258 records x 128B
#define CONV_SMEM (2 * HSTRIP_B)      // 66048 (== st epilogue 64*258*4)

template <bool IS_CONV2>
__global__ __launch_bounds__(256, 2)
void conv_frag_kernel(const __nv_bfloat16* __restrict__ pad,
                      const uint32_t* __restrict__ wfrag,
                      const float* __restrict__ bias,
                      const float* __restrict__ prelu_a,
                      __nv_bfloat16* __restrict__ outp)
{
    extern __shared__ char smem[];
    float* st = (float*)smem;
    __shared__ float s_b[64], s_a[64];

    const int tid = threadIdx.x, lane = tid & 31, wid = tid >> 5;
    const int wm = wid & 3, wn = wid >> 2;
    const int y0 = blockIdx.x, b = blockIdx.y;
    const uint32_t su = s2u(smem);

    if (tid < 64) { s_b[tid] = bias[tid]; s_a[tid] = IS_CONV2 ? 0.f : prelu_a[tid]; }

    float acc[4][4][4];
#pragma unroll
    for (int f = 0; f < 4; f++)
#pragma unroll
        for (int g = 0; g < 4; g++)
#pragma unroll
            for (int c = 0; c < 4; c++) acc[f][g][c] = 0.0f;

    const int mrow = wm * 64 + (lane & 15);
    const int asel = lane >> 4;
    const uint4* wf4 = (const uint4*)wfrag;

    // stage s: row = s>>1, chunk c2 = s&1, into buffer s&1.
    // half-record layout: words 0-3 = hi of chunk (64B), words 4-7 = lo of chunk.
    auto stage = [&](int s) {
        const int row = s >> 1, c2 = s & 1;
        const char* src = (const char*)(pad +
            (((size_t)b * PADW + (y0 + row)) * PADW) * 128);
        const uint32_t du = su + (s & 1) * HSTRIP_B;
        for (int i = tid; i < 2064; i += 256) {
            int p = i >> 3, w = i & 7;
            int soff = p * 256 + ((w < 4) ? (c2 * 64 + w * 16)
                                          : (128 + c2 * 64 + (w - 4) * 16));
            cp16(du + p * 128 + ((w ^ (p & 7)) << 4), src + soff);
        }
        CP_COMMIT();
    };

    stage(0);
    stage(1);

    for (int s = 0; s < 6; s++) {
        if (s < 5) CP_WAIT1(); else CP_WAIT0();
        __syncthreads();
        const int c2 = s & 1, ky = s >> 1;
        const uint32_t bu = su + (s & 1) * HSTRIP_B;
#pragma unroll
        for (int kx = 0; kx < 3; kx++) {
            const uint4* wb = wf4 + ((size_t)((ky * 3 + kx) * 2 + wn) * 16) * 32 + lane;
#pragma unroll
            for (int ksl = 0; ksl < 2; ksl++) {
                const int ks = c2 * 2 + ksl;
                uint32_t ah[4][4], al[4][4];
#pragma unroll
                for (int f = 0; f < 4; f++) {
                    int row = kx + mrow + f * 16;
                    uint32_t base = bu + row * 128;
                    int chi = ksl * 2 + asel;          // 0..3 (hi half)
                    ldsm_x4(base + (((chi    ) ^ (row & 7)) << 4),
                            ah[f][0], ah[f][1], ah[f][2], ah[f][3]);
                    ldsm_x4(base + (((chi + 4) ^ (row & 7)) << 4),
                            al[f][0], al[f][1], al[f][2], al[f][3]);
                }
#pragma unroll
                for (int h = 0; h < 2; h++) {
                    uint4 BH = wb[((0 * 4 + ks) * 2 + h) * 32];
                    uint4 BL = wb[((1 * 4 + ks) * 2 + h) * 32];
                    uint32_t bh[4] = { BH.x, BH.y, BH.z, BH.w };
                    uint32_t bl[4] = { BL.x, BL.y, BL.z, BL.w };
#pragma unroll
                    for (int gg = 0; gg < 2; gg++) {
                        int g = 2 * h + gg;
#pragma unroll
                        for (int f = 0; f < 4; f++) {
                            mma16816(acc[f][g], ah[f], bh[2 * gg], bh[2 * gg + 1]);
                            mma16816(acc[f][g], al[f], bh[2 * gg], bh[2 * gg + 1]);
                            mma16816(acc[f][g], ah[f], bl[2 * gg], bl[2 * gg + 1]);
                        }
                    }
                }
            }
        }
        __syncthreads();
        if (s < 4) stage(s + 2);
    }

    // ---- epilogue: transpose via st (reuses both buffers), emit records ------
#pragma unroll
    for (int f = 0; f < 4; f++)
#pragma unroll
        for (int g = 0; g < 4; g++)
#pragma unroll
            for (int c = 0; c < 4; c++) {
                int m = wm * 64 + f * 16 + (lane >> 2) + ((c >> 1) << 3);
                int n = wn * 32 + g * 8 + ((lane & 3) << 1) + (c & 1);
                st[n * 258 + m] = acc[f][g][c] + s_b[n];
            }
    __syncthreads();

    {
        float v[64];
#pragma unroll
        for (int c = 0; c < 64; c++) v[c] = st[c * 258 + tid];

        if (!IS_CONV2) {
#pragma unroll
            for (int c = 0; c < 64; c++) v[c] = v[c] > 0.f ? v[c] : s_a[c] * v[c];
        } else {
            float sum = 0.f, mx = -FLT_MAX;
#pragma unroll
            for (int c = 0; c < 64; c++) { sum += v[c]; mx = fmaxf(mx, v[c]); }
            const int gp = y0 * 256 + tid;
            g_avg[b * HWN + gp] = sum * (1.0f / CH);
            g_max[b * HWN + gp] = mx;
        }

        uint4 rec[16];
#pragma unroll
        for (int j = 0; j < 16; j++) {
            int k0 = (j & 7) * 8;
            bool lo = j >= 8;
            uint32_t* wp = (uint32_t*)&rec[j];
#pragma unroll
            for (int q = 0; q < 4; q++) {
                float f0 = v[k0 + 2 * q], f1 = v[k0 + 2 * q + 1];
                if (lo) {
                    f0 -= __bfloat162float(__float2bfloat16(f0));
                    f1 -= __bfloat162float(__float2bfloat16(f1));
                }
                wp[q] = pack2bf(f0, f1);
            }
        }

        if (!IS_CONV2) {
            uint4* base = (uint4*)(outp + (size_t)b * PADW * PADW * 128);
            int rmir = (y0 == 1) ? 0 : (y0 == 254 ? 257 : -1);
            int cmir = (tid == 1) ? 0 : (tid == 254 ? 257 : -1);
            store_rec_mirror(base, y0 + 1, tid + 1, rmir, cmir, rec);
        } else {
            uint4* dst = (uint4*)(outp + (((size_t)b << 16) + y0 * 256 + tid) * 128);
#pragma unroll
            for (int j = 0; j < 16; j++) dst[j] = rec[j];
        }
    }

    if (IS_CONV2) {
        int oc = tid >> 2;
        float s = 0.0f;
        for (int p = (tid & 3); p < 256; p += 4) s += st[oc * 258 + p];
        s += __shfl_xor_sync(0xFFFFFFFFu, s, 1);
        s += __shfl_xor_sync(0xFFFFFFFFu, s, 2);
        if ((tid & 3) == 0) atomicAdd(&g_chansum[b * CH + oc], s);
    }
}

// ---------------- spatial attention conv -------------------------------------
__global__ __launch_bounds__(256)
void sa_kernel(const float* __restrict__ sa_w, const float* __restrict__ sa_b)
{
    int p = blockIdx.x * 256 + threadIdx.x;
    int b = blockIdx.y;
    int x = p & (IMG_W - 1);
    int y = p >> 8;
    float s = sa_b[0];
#pragma unroll
    for (int ky = 0; ky < 3; ky++) {
        int gy = reflect(y + ky - 1, IMG_H);
#pragma unroll
        for (int kx = 0; kx < 3; kx++) {
            int gx = reflect(x + kx - 1, IMG_W);
            int q = b * HWN + gy * IMG_W + gx;
            s = fmaf(sa_w[ky * 3 + kx],     g_avg[q], s);
            s = fmaf(sa_w[9 + ky * 3 + kx], g_max[q], s);
        }
    }
    g_sg[b * HWN + p] = 1.0f / (1.0f + expf(-s));
}

// ---------------- per-batch small dense math + K prepack ---------------------
__global__ __launch_bounds__(256)
void small_kernel(const float* __restrict__ h_in,
                  const float* __restrict__ ca_w1, const float* __restrict__ ca_b1,
                  const float* __restrict__ ca_a,
                  const float* __restrict__ ca_w2, const float* __restrict__ ca_b2,
                  const float* __restrict__ fc_w,  const float* __restrict__ fc_b,
                  const float* __restrict__ k1_w,  const float* __restrict__ k1_b,
                  const float* __restrict__ k2_w,  const float* __restrict__ k2_b,
                  const float* __restrict__ k3_w,  const float* __restrict__ k3_b)
{
    __shared__ float g[64], t1[32], cv[64], hv[16], t0[16], ta[32], tb[32];
    const int b = blockIdx.x;
    const int tid = threadIdx.x;

    if (tid < 64) g[tid] = g_chansum[b * CH + tid] * (1.0f / HWN);
    if (tid < 16) hv[tid] = h_in[b * 16 + tid];
    __syncthreads();

    if (tid < 32) {
        float s = ca_b1[tid];
        for (int c = 0; c < 64; c++) s = fmaf(ca_w1[tid * 64 + c], g[c], s);
        t1[tid] = s > 0.0f ? s : ca_a[tid] * s;
    }
    if (tid >= 32 && tid < 48) {
        int j = tid - 32;
        float s = fc_b[j];
        for (int c = 0; c < 16; c++) s = fmaf(fc_w[j * 16 + c], hv[c], s);
        t0[j] = s >= 0.0f ? s : 0.01f * s;
    }
    __syncthreads();

    if (tid < 64) {
        float s = ca_b2[tid];
        for (int j = 0; j < 32; j++) s = fmaf(ca_w2[tid * 32 + j], t1[j], s);
        cv[tid] = 1.0f / (1.0f + expf(-s));
    }
    if (tid >= 64 && tid < 96) {
        int j = tid - 64;
        float s = k1_b[j];
        for (int c = 0; c < 16; c++) s = fmaf(k1_w[j * 16 + c], t0[c], s);
        ta[j] = s >= 0.0f ? s : 0.01f * s;
    }
    __syncthreads();

    if (tid < 32) {
        float s = k2_b[tid];
        for (int j = 0; j < 32; j++) s = fmaf(k2_w[tid * 32 + j], ta[j], s);
        tb[tid] = s >= 0.0f ? s : 0.01f * s;
    }
    __syncthreads();

    for (int idx = tid; idx < 8192; idx += 256) {
        float s = k3_b[idx];
        for (int j = 0; j < 32; j++) s = fmaf(k3_w[idx * 32 + j], tb[j], s);
        int o = idx >> 7, i = idx & 127;
        int which = (i >= 64);
        int ch = i & 63;
        float val = which ? s * cv[ch] : s;
        __nv_bfloat16 hi = __float2bfloat16(val);
        __nv_bfloat16 lo = __float2bfloat16(val - __bfloat162float(hi));
        size_t base = (size_t)b * 16384 + (which * 64 + o) * 128 + ch;
        g_Kpk[base]      = hi;
        g_Kpk[base + 64] = lo;
    }
}

// ---------------- final: tensor-core dual matvec + residual ------------------
#define PF  136
#define STP 132
#define KM_B   34816
#define SLR_B  32768
#define FIN_SMEM (KM_B + SLR_B + 512)   // 68096

__global__ __launch_bounds__(256)
void final_kernel(const float* __restrict__ hc_bias,
                  const float* __restrict__ x,
                  float* __restrict__ out)
{
    extern __shared__ char smem[];
    __nv_bfloat16* sKm = (__nv_bfloat16*)smem;       // [128 rows][PF]
    char* slabR = smem + KM_B;                       // 128 records x 256B, swizzled
    float* ssg = (float*)(smem + KM_B + SLR_B);      // [128]
    float* st  = (float*)smem;                       // epilogue reuse
    __shared__ float sbias[64];

    const int tid  = threadIdx.x;
    const int lane = tid & 31;
    const int wid  = tid >> 5;
    const int wm   = wid & 3;
    const int wn   = wid >> 2;
    const int b    = blockIdx.y;
    const int p0   = blockIdx.x * 128;
    const uint32_t sr_u = s2u(slabR);

    if (tid < 64) sbias[tid] = hc_bias[tid];
    const __nv_bfloat16* ksrc = g_Kpk + (size_t)b * 16384;
    for (int idx = tid; idx < 2048; idx += 256) {
        int r = idx >> 4, v = (idx & 15) << 3;
        *(uint4*)(sKm + r * PF + v) = *(const uint4*)(ksrc + r * 128 + v);
    }
    {
        const char* src = (const char*)(g_rcl + (((size_t)b << 16) + p0) * 128);
        for (int i = tid; i < 2048; i += 256) {
            int p = i >> 4, j = i & 15;
            cp16(sr_u + p * 256 + ((j ^ (p & 7)) << 4), src + (size_t)i * 16);
        }
        CP_COMMIT();
    }
    if (tid < 128) ssg[tid] = g_sg[b * HWN + p0 + tid];
    CP_WAIT0();
    __syncthreads();

    const uint32_t km_u = s2u(sKm);
    const int mrow = wm * 32 + (lane & 15);
    const int asel = lane >> 4;
    const int bg    = lane >> 4;
    const int bk    = ((lane >> 3) & 1) << 3;
    const int blrow = lane & 7;

    float acc[2][2][4][4];
#pragma unroll
    for (int s = 0; s < 2; s++)
#pragma unroll
        for (int f = 0; f < 2; f++)
#pragma unroll
            for (int g = 0; g < 4; g++)
#pragma unroll
                for (int c = 0; c < 4; c++) acc[s][f][g][c] = 0.0f;

#pragma unroll
    for (int ks = 0; ks < 4; ks++) {
        uint32_t ah[2][4], al[2][4];
#pragma unroll
        for (int f = 0; f < 2; f++) {
            int row = mrow + f * 16;
            uint32_t base = sr_u + row * 256;
            int chi = ks * 2 + asel;
            ldsm_x4(base + (((chi    ) ^ (row & 7)) << 4),
                    ah[f][0], ah[f][1], ah[f][2], ah[f][3]);
            ldsm_x4(base + (((chi + 8) ^ (row & 7)) << 4),
                    al[f][0], al[f][1], al[f][2], al[f][3]);
        }
#pragma unroll
        for (int s = 0; s < 2; s++) {
#pragma unroll
            for (int gp = 0; gp < 2; gp++) {
                int brow = s * 64 + wn * 32 + (2 * gp + bg) * 8 + blrow;
                uint32_t bb = km_u + (uint32_t)((brow * PF + bk + ks * 16) * 2);
                uint32_t bh0, bh1, bh2, bh3, bl0, bl1, bl2, bl3;
                ldsm_x4(bb,       bh0, bh1, bh2, bh3);
                ldsm_x4(bb + 128, bl0, bl1, bl2, bl3);
#pragma unroll
                for (int f = 0; f < 2; f++) {
                    mma16816(acc[s][f][2 * gp],     ah[f], bh0, bh1);
                    mma16816(acc[s][f][2 * gp],     al[f], bh0, bh1);
                    mma16816(acc[s][f][2 * gp],     ah[f], bl0, bl1);
                    mma16816(acc[s][f][2 * gp + 1], ah[f], bh2, bh3);
                    mma16816(acc[s][f][2 * gp + 1], al[f], bh2, bh3);
                    mma16816(acc[s][f][2 * gp + 1], ah[f], bl2, bl3);
                }
            }
        }
    }

    __syncthreads();
#pragma unroll
    for (int f = 0; f < 2; f++)
#pragma unroll
        for (int g = 0; g < 4; g++)
#pragma unroll
            for (int c = 0; c < 4; c++) {
                int m = wm * 32 + f * 16 + (lane >> 2) + ((c >> 1) << 3);
                int n = wn * 32 + g * 8 + ((lane & 3) << 1) + (c & 1);
                st[n * STP + m] = ssg[m] * acc[0][f][g][c] + acc[1][f][g][c] + sbias[n];
            }
    __syncthreads();

    const size_t obase = (size_t)b * CH * HWN + p0;
    for (int idx = tid; idx < 2048; idx += 256) {
        int oc = idx >> 5, v = (idx & 31) << 2;
        size_t gi = obase + (size_t)oc * HWN + v;
        float4 xv = *(const float4*)&x[gi];
        float4 sv = *(const float4*)&st[oc * STP + v];
        float4 ov = { xv.x + sv.x, xv.y + sv.y, xv.z + sv.z, xv.w + sv.w };
        *(float4*)&out[gi] = ov;
    }
}

// ---------------- launch ----------------------------------------------------
extern "C" void kernel_launch(void* const* d_in, const int* in_sizes, int n_in,
                              void* d_out, int out_size)
{
    const float* x       = (const float*)d_in[0];
    const float* h       = (const float*)d_in[1];
    const float* conv1_w = (const float*)d_in[2];
    const float* conv1_b = (const float*)d_in[3];
    const float* prelu_a = (const float*)d_in[4];
    const float* conv2_w = (const float*)d_in[5];
    const float* conv2_b = (const float*)d_in[6];
    const float* sa_w    = (const float*)d_in[7];
    const float* sa_b    = (const float*)d_in[8];
    const float* ca_w1   = (const float*)d_in[9];
    const float* ca_b1   = (const float*)d_in[10];
    const float* ca_a    = (const float*)d_in[11];
    const float* ca_w2   = (const float*)d_in[12];
    const float* ca_b2   = (const float*)d_in[13];
    const float* fc_w    = (const float*)d_in[14];
    const float* fc_b    = (const float*)d_in[15];
    const float* k1_w    = (const float*)d_in[16];
    const float* k1_b    = (const float*)d_in[17];
    const float* k2_w    = (const float*)d_in[18];
    const float* k2_b    = (const float*)d_in[19];
    const float* k3_w    = (const float*)d_in[20];
    const float* k3_b    = (const float*)d_in[21];
    const float* hc_bias = (const float*)d_in[22];
    float* out = (float*)d_out;

    __nv_bfloat16 *padx = nullptr, *pad1 = nullptr, *rcl = nullptr;
    uint32_t* wfr = nullptr;
    cudaGetSymbolAddress((void**)&padx, g_padx);
    cudaGetSymbolAddress((void**)&pad1, g_pad1);
    cudaGetSymbolAddress((void**)&rcl,  g_rcl);
    cudaGetSymbolAddress((void**)&wfr,  g_Wfrag);

    static bool attr_set = false;
    if (!attr_set) {
        cudaFuncSetAttribute(conv_frag_kernel<false>,
                             cudaFuncAttributeMaxDynamicSharedMemorySize, CONV_SMEM);
        cudaFuncSetAttribute(conv_frag_kernel<true>,
                             cudaFuncAttributeMaxDynamicSharedMemorySize, CONV_SMEM);
        cudaFuncSetAttribute(final_kernel,
                             cudaFuncAttributeMaxDynamicSharedMemorySize, FIN_SMEM);
        attr_set = true;
    }

    init_kernel<<<2, 256>>>();
    wfrag_kernel<<<288, 256>>>(conv1_w, conv2_w);
    pad_input_kernel<<<dim3(256, NB), 256>>>(x);

    dim3 cgrid(IMG_H, NB);
    conv_frag_kernel<false><<<cgrid, 256, CONV_SMEM>>>(padx, wfr, conv1_b, prelu_a, pad1);
    conv_frag_kernel<true ><<<cgrid, 256, CONV_SMEM>>>(pad1, wfr + 36864, conv2_b, prelu_a, rcl);

    sa_kernel<<<dim3(HWN / 256, NB), 256>>>(sa_w, sa_b);

    small_kernel<<<NB, 256>>>(h, ca_w1, ca_b1, ca_a, ca_w2, ca_b2,
                              fc_w, fc_b, k1_w, k1_b, k2_w, k2_b, k3_w, k3_b);

    final_kernel<<<dim3(HWN / 128, NB), 256, FIN_SMEM>>>(hc_bias, x, out);
}

// round 14
// speedup vs baseline: 1.6036x; 1.0498x over previous
#include <cuda_runtime.h>
#include <cuda_bf16.h>
#include <math.h>
#include <float.h>
#include <stdint.h>

#define CH    64
#define IMG_W 256
#define IMG_H 256
#define HWN   65536
#define NB    8
#define PADW  258

// ---------------- device-global scratch -------------------------------------
__device__ __align__(16) __nv_bfloat16 g_padx[NB * PADW * PADW * 128];
__device__ __align__(16) __nv_bfloat16 g_pad1[NB * PADW * PADW * 128];
__device__ __align__(16) __nv_bfloat16 g_rcl [NB * HWN * 128];
__device__ __align__(16) float g_avg[NB * HWN];
__device__ __align__(16) float g_max[NB * HWN];
__device__ float g_chansum[NB * CH];
__device__ __align__(16) __nv_bfloat16 g_Kpk[NB * 2 * 64 * 128];
__device__ __align__(16) uint32_t g_Wfrag[73728];   // [cv][t][wn][sb][ks][h][lane][e]

// ---------------- helpers ----------------------------------------------------
__device__ __forceinline__ int reflect(int v, int n) {
    if (v < 0) v = -v;
    if (v >= n) v = 2 * n - 2 - v;
    return v;
}
__device__ __forceinline__ uint32_t s2u(const void* p) {
    return (uint32_t)__cvta_generic_to_shared(p);
}
__device__ __forceinline__ uint32_t pack2bf(float a, float b) {
    return ((uint32_t)__bfloat16_as_ushort(__float2bfloat16(a))) |
           ((uint32_t)__bfloat16_as_ushort(__float2bfloat16(b)) << 16);
}
__device__ __forceinline__ void ldsm_x4(uint32_t addr, uint32_t& r0, uint32_t& r1,
                                        uint32_t& r2, uint32_t& r3) {
    asm volatile("ldmatrix.sync.aligned.m8n8.x4.shared.b16 {%0,%1,%2,%3}, [%4];"
                 : "=r"(r0), "=r"(r1), "=r"(r2), "=r"(r3) : "r"(addr));
}
__device__ __forceinline__ void mma16816(float* c, const uint32_t* a,
                                         uint32_t b0, uint32_t b1) {
    asm volatile("mma.sync.aligned.m16n8k16.row.col.f32.bf16.bf16.f32 "
                 "{%0,%1,%2,%3}, {%4,%5,%6,%7}, {%8,%9}, {%0,%1,%2,%3};"
                 : "+f"(c[0]), "+f"(c[1]), "+f"(c[2]), "+f"(c[3])
                 : "r"(a[0]), "r"(a[1]), "r"(a[2]), "r"(a[3]), "r"(b0), "r"(b1));
}
__device__ __forceinline__ void cp16cg(uint32_t dst, const void* src) {
    asm volatile("cp.async.cg.shared.global [%0], [%1], 16;" :: "r"(dst), "l"(src));
}
#define CP_COMMIT() asm volatile("cp.async.commit_group;" ::: "memory")
#define CP_WAIT0()  asm volatile("cp.async.wait_group 0;" ::: "memory")

// ---------------- init ----------------
__global__ void init_kernel() {
    int i = blockIdx.x * blockDim.x + threadIdx.x;
    if (i < NB * CH) g_chansum[i] = 0.0f;
}

// ---------------- weight frag prepack (lane-fastest, coalesced) --------------
__global__ __launch_bounds__(256)
void wfrag_kernel(const float* __restrict__ w1, const float* __restrict__ w2) {
    int idx = blockIdx.x * 256 + threadIdx.x;
    if (idx >= 73728) return;
    int e    = idx & 3;
    int lane = (idx >> 2) & 31;
    int h    = (idx >> 7) & 1;
    int ks   = (idx >> 8) & 3;
    int sb   = (idx >> 10) & 1;
    int wn   = (idx >> 11) & 1;
    int rest = idx >> 12;
    int t    = rest % 9;
    int cv   = rest / 9;
    int nt = 2 * h + (e >> 1);
    int rr = e & 1;
    int n  = wn * 32 + nt * 8 + (lane >> 2);
    int k0 = ks * 16 + rr * 8 + (lane & 3) * 2;
    const float* w = cv ? w2 : w1;
    uint32_t out = 0;
#pragma unroll
    for (int q = 0; q < 2; q++) {
        int ch = k0 + q;
        float v = w[n * 576 + ch * 9 + t];
        __nv_bfloat16 hi = __float2bfloat16(v);
        __nv_bfloat16 bf = sb ? __float2bfloat16(v - __bfloat162float(hi)) : hi;
        out |= ((uint32_t)__bfloat16_as_ushort(bf)) << (16 * q);
    }
    g_Wfrag[idx] = out;
}

// ---------------- record store with reflect mirrors --------------------------
__device__ __forceinline__ void store_rec_mirror(uint4* base, int row0, int col0,
                                                 int row1, int col1,
                                                 const uint4* rec) {
    int rows[2] = { row0, row1 };
    int cols[2] = { col0, col1 };
    int nr = (row1 >= 0) ? 2 : 1;
    int nc = (col1 >= 0) ? 2 : 1;
    for (int r = 0; r < nr; r++)
        for (int c = 0; c < nc; c++) {
            uint4* d = base + ((size_t)rows[r] * PADW + cols[c]) * 16;
#pragma unroll
            for (int j = 0; j < 16; j++) d[j] = rec[j];
        }
}

// ---------------- input prepass: fp32 NCHW -> padded ch-last bf16 hi/lo ------
__global__ __launch_bounds__(256)
void pad_input_kernel(const float* __restrict__ x) {
    const int y = blockIdx.x, b = blockIdx.y, px = threadIdx.x;
    float v[64];
#pragma unroll
    for (int c = 0; c < 64; c++)
        v[c] = x[(((size_t)(b * 64 + c)) << 16) + y * 256 + px];
    uint4 rec[16];
#pragma unroll
    for (int j = 0; j < 16; j++) {
        int k0 = (j & 7) * 8;
        bool lo = j >= 8;
        uint32_t* wp = (uint32_t*)&rec[j];
#pragma unroll
        for (int q = 0; q < 4; q++) {
            float f0 = v[k0 + 2 * q], f1 = v[k0 + 2 * q + 1];
            if (lo) {
                f0 -= __bfloat162float(__float2bfloat16(f0));
                f1 -= __bfloat162float(__float2bfloat16(f1));
            }
            wp[q] = pack2bf(f0, f1);
        }
    }
    uint4* base = (uint4*)(g_padx + (size_t)b * PADW * PADW * 128);
    int rmir = (y == 1) ? 0 : (y == 254 ? 257 : -1);
    int cmir = (px == 1) ? 0 : (px == 254 ? 257 : -1);
    store_rec_mirror(base, y + 1, px + 1, rmir, cmir, rec);
}

// ---------------- conv: mma.sync + frag-LDG(cg) weights, M=256/CTA (R9) ------
#define STRIP_B 66048     // 258 records x 256B (== st: 64*258*4)

template <bool IS_CONV2>
__global__ __launch_bounds__(256, 2)
void conv_frag_kernel(const __nv_bfloat16* __restrict__ pad,
                      const uint32_t* __restrict__ wfrag,
                      const float* __restrict__ bias,
                      const float* __restrict__ prelu_a,
                      __nv_bfloat16* __restrict__ outp)
{
    extern __shared__ char smem[];
    float* st = (float*)smem;
    __shared__ float s_b[64], s_a[64];

    const int tid = threadIdx.x, lane = tid & 31, wid = tid >> 5;
    const int wm = wid & 3, wn = wid >> 2;
    const int y0 = blockIdx.x, b = blockIdx.y;
    const uint32_t su = s2u(smem);

    if (tid < 64) { s_b[tid] = bias[tid]; s_a[tid] = IS_CONV2 ? 0.f : prelu_a[tid]; }

    float acc[4][4][4];
#pragma unroll
    for (int f = 0; f < 4; f++)
#pragma unroll
        for (int g = 0; g < 4; g++)
#pragma unroll
            for (int c = 0; c < 4; c++) acc[f][g][c] = 0.0f;

    const int mrow = wm * 64 + (lane & 15);
    const int asel = lane >> 4;
    const uint4* wf4 = (const uint4*)wfrag;

#pragma unroll
    for (int ky = 0; ky < 3; ky++) {
        __syncthreads();
        {
            const char* src = (const char*)(pad +
                (((size_t)b * PADW + (y0 + ky)) * PADW) * 128);
            for (int i = tid; i < 4128; i += 256) {
                int p = i >> 4, j = i & 15;
                cp16cg(su + p * 256 + ((j ^ (p & 7)) << 4), src + (size_t)i * 16);
            }
            CP_COMMIT(); CP_WAIT0();
        }
        __syncthreads();
#pragma unroll
        for (int kx = 0; kx < 3; kx++) {
            const uint4* wb = wf4 + ((size_t)((ky * 3 + kx) * 2 + wn) * 16) * 32 + lane;
#pragma unroll
            for (int ks = 0; ks < 4; ks++) {
                uint32_t ah[4][4], al[4][4];
#pragma unroll
                for (int f = 0; f < 4; f++) {
                    int row = kx + mrow + f * 16;
                    uint32_t base = su + row * 256;
                    int chi = ks * 2 + asel;
                    ldsm_x4(base + (((chi    ) ^ (row & 7)) << 4),
                            ah[f][0], ah[f][1], ah[f][2], ah[f][3]);
                    ldsm_x4(base + (((chi + 8) ^ (row & 7)) << 4),
                            al[f][0], al[f][1], al[f][2], al[f][3]);
                }
#pragma unroll
                for (int h = 0; h < 2; h++) {
                    uint4 BH = __ldcg(&wb[((0 * 4 + ks) * 2 + h) * 32]);
                    uint4 BL = __ldcg(&wb[((1 * 4 + ks) * 2 + h) * 32]);
                    uint32_t bh[4] = { BH.x, BH.y, BH.z, BH.w };
                    uint32_t bl[4] = { BL.x, BL.y, BL.z, BL.w };
#pragma unroll
                    for (int gg = 0; gg < 2; gg++) {
                        int g = 2 * h + gg;
#pragma unroll
                        for (int f = 0; f < 4; f++) {
                            mma16816(acc[f][g], ah[f], bh[2 * gg], bh[2 * gg + 1]);
                            mma16816(acc[f][g], al[f], bh[2 * gg], bh[2 * gg + 1]);
                            mma16816(acc[f][g], ah[f], bl[2 * gg], bl[2 * gg + 1]);
                        }
                    }
                }
            }
        }
    }

    // ---- epilogue: transpose via st, emit ch-last records ----
    __syncthreads();
#pragma unroll
    for (int f = 0; f < 4; f++)
#pragma unroll
        for (int g = 0; g < 4; g++)
#pragma unroll
            for (int c = 0; c < 4; c++) {
                int m = wm * 64 + f * 16 + (lane >> 2) + ((c >> 1) << 3);
                int n = wn * 32 + g * 8 + ((lane & 3) << 1) + (c & 1);
                st[n * 258 + m] = acc[f][g][c] + s_b[n];
            }
    __syncthreads();

    {
        float v[64];
#pragma unroll
        for (int c = 0; c < 64; c++) v[c] = st[c * 258 + tid];

        if (!IS_CONV2) {
#pragma unroll
            for (int c = 0; c < 64; c++) v[c] = v[c] > 0.f ? v[c] : s_a[c] * v[c];
        } else {
            float sum = 0.f, mx = -FLT_MAX;
#pragma unroll
            for (int c = 0; c < 64; c++) { sum += v[c]; mx = fmaxf(mx, v[c]); }
            const int gp = y0 * 256 + tid;
            g_avg[b * HWN + gp] = sum * (1.0f / CH);
            g_max[b * HWN + gp] = mx;
        }

        uint4 rec[16];
#pragma unroll
        for (int j = 0; j < 16; j++) {
            int k0 = (j & 7) * 8;
            bool lo = j >= 8;
            uint32_t* wp = (uint32_t*)&rec[j];
#pragma unroll
            for (int q = 0; q < 4; q++) {
                float f0 = v[k0 + 2 * q], f1 = v[k0 + 2 * q + 1];
                if (lo) {
                    f0 -= __bfloat162float(__float2bfloat16(f0));
                    f1 -= __bfloat162float(__float2bfloat16(f1));
                }
                wp[q] = pack2bf(f0, f1);
            }
        }

        if (!IS_CONV2) {
            uint4* base = (uint4*)(outp + (size_t)b * PADW * PADW * 128);
            int rmir = (y0 == 1) ? 0 : (y0 == 254 ? 257 : -1);
            int cmir = (tid == 1) ? 0 : (tid == 254 ? 257 : -1);
            store_rec_mirror(base, y0 + 1, tid + 1, rmir, cmir, rec);
        } else {
            uint4* dst = (uint4*)(outp + (((size_t)b << 16) + y0 * 256 + tid) * 128);
#pragma unroll
            for (int j = 0; j < 16; j++) dst[j] = rec[j];
        }
    }

    if (IS_CONV2) {
        int oc = tid >> 2;
        float s = 0.0f;
        for (int p = (tid & 3); p < 256; p += 4) s += st[oc * 258 + p];
        s += __shfl_xor_sync(0xFFFFFFFFu, s, 1);
        s += __shfl_xor_sync(0xFFFFFFFFu, s, 2);
        if ((tid & 3) == 0) atomicAdd(&g_chansum[b * CH + oc], s);
    }
}

// ---------------- per-batch small dense math + K prepack ---------------------
__global__ __launch_bounds__(256)
void small_kernel(const float* __restrict__ h_in,
                  const float* __restrict__ ca_w1, const float* __restrict__ ca_b1,
                  const float* __restrict__ ca_a,
                  const float* __restrict__ ca_w2, const float* __restrict__ ca_b2,
                  const float* __restrict__ fc_w,  const float* __restrict__ fc_b,
                  const float* __restrict__ k1_w,  const float* __restrict__ k1_b,
                  const float* __restrict__ k2_w,  const float* __restrict__ k2_b,
                  const float* __restrict__ k3_w,  const float* __restrict__ k3_b)
{
    __shared__ float g[64], t1[32], cv[64], hv[16], t0[16], ta[32], tb[32];
    const int b = blockIdx.x;
    const int tid = threadIdx.x;

    if (tid < 64) g[tid] = g_chansum[b * CH + tid] * (1.0f / HWN);
    if (tid < 16) hv[tid] = h_in[b * 16 + tid];
    __syncthreads();

    if (tid < 32) {
        float s = ca_b1[tid];
        for (int c = 0; c < 64; c++) s = fmaf(ca_w1[tid * 64 + c], g[c], s);
        t1[tid] = s > 0.0f ? s : ca_a[tid] * s;
    }
    if (tid >= 32 && tid < 48) {
        int j = tid - 32;
        float s = fc_b[j];
        for (int c = 0; c < 16; c++) s = fmaf(fc_w[j * 16 + c], hv[c], s);
        t0[j] = s >= 0.0f ? s : 0.01f * s;
    }
    __syncthreads();

    if (tid < 64) {
        float s = ca_b2[tid];
        for (int j = 0; j < 32; j++) s = fmaf(ca_w2[tid * 32 + j], t1[j], s);
        cv[tid] = 1.0f / (1.0f + expf(-s));
    }
    if (tid >= 64 && tid < 96) {
        int j = tid - 64;
        float s = k1_b[j];
        for (int c = 0; c < 16; c++) s = fmaf(k1_w[j * 16 + c], t0[c], s);
        ta[j] = s >= 0.0f ? s : 0.01f * s;
    }
    __syncthreads();

    if (tid < 32) {
        float s = k2_b[tid];
        for (int j = 0; j < 32; j++) s = fmaf(k2_w[tid * 32 + j], ta[j], s);
        tb[tid] = s >= 0.0f ? s : 0.01f * s;
    }
    __syncthreads();

    for (int idx = tid; idx < 8192; idx += 256) {
        float s = k3_b[idx];
        for (int j = 0; j < 32; j++) s = fmaf(k3_w[idx * 32 + j], tb[j], s);
        int o = idx >> 7, i = idx & 127;
        int which = (i >= 64);
        int ch = i & 63;
        float val = which ? s * cv[ch] : s;
        __nv_bfloat16 hi = __float2bfloat16(val);
        __nv_bfloat16 lo = __float2bfloat16(val - __bfloat162float(hi));
        size_t base = (size_t)b * 16384 + (which * 64 + o) * 128 + ch;
        g_Kpk[base]      = hi;
        g_Kpk[base + 64] = lo;
    }
}

// ---------------- final: tensor-core dual matvec + fused SA + residual -------
#define PF  136
#define STP 132
#define KM_B   34816
#define SLR_B  32768
#define FIN_SMEM (KM_B + SLR_B + 512)   // 68096

__global__ __launch_bounds__(256)
void final_kernel(const float* __restrict__ hc_bias,
                  const float* __restrict__ sa_w,
                  const float* __restrict__ sa_b,
                  const float* __restrict__ x,
                  float* __restrict__ out)
{
    extern __shared__ char smem[];
    __nv_bfloat16* sKm = (__nv_bfloat16*)smem;       // [128 rows][PF]
    char* slabR = smem + KM_B;                       // 128 records x 256B, swizzled
    float* ssg = (float*)(smem + KM_B + SLR_B);      // [128]
    float* st  = (float*)smem;                       // epilogue reuse
    __shared__ float sbias[64];

    const int tid  = threadIdx.x;
    const int lane = tid & 31;
    const int wid  = tid >> 5;
    const int wm   = wid & 3;
    const int wn   = wid >> 2;
    const int b    = blockIdx.y;
    const int p0   = blockIdx.x * 128;
    const uint32_t sr_u = s2u(slabR);

    if (tid < 64) sbias[tid] = hc_bias[tid];
    const __nv_bfloat16* ksrc = g_Kpk + (size_t)b * 16384;
    for (int idx = tid; idx < 2048; idx += 256) {
        int r = idx >> 4, v = (idx & 15) << 3;
        *(uint4*)(sKm + r * PF + v) = __ldcg((const uint4*)(ksrc + r * 128 + v));
    }
    {
        const char* src = (const char*)(g_rcl + (((size_t)b << 16) + p0) * 128);
        for (int i = tid; i < 2048; i += 256) {
            int p = i >> 4, j = i & 15;
            cp16cg(sr_u + p * 256 + ((j ^ (p & 7)) << 4), src + (size_t)i * 16);
        }
        CP_COMMIT();
    }
    // fused spatial attention: sg for this block's 128 pixels
    if (tid < 128) {
        int gp = p0 + tid;
        int xx = gp & (IMG_W - 1);
        int yy = gp >> 8;
        float s = sa_b[0];
#pragma unroll
        for (int ky = 0; ky < 3; ky++) {
            int gy = reflect(yy + ky - 1, IMG_H);
#pragma unroll
            for (int kx = 0; kx < 3; kx++) {
                int gx = reflect(xx + kx - 1, IMG_W);
                int q = b * HWN + gy * IMG_W + gx;
                s = fmaf(sa_w[ky * 3 + kx],     g_avg[q], s);
                s = fmaf(sa_w[9 + ky * 3 + kx], g_max[q], s);
            }
        }
        ssg[tid] = 1.0f / (1.0f + expf(-s));
    }
    CP_WAIT0();
    __syncthreads();

    const uint32_t km_u = s2u(sKm);
    const int mrow = wm * 32 + (lane & 15);
    const int asel = lane >> 4;
    const int bg    = lane >> 4;
    const int bk    = ((lane >> 3) & 1) << 3;
    const int blrow = lane & 7;

    float acc[2][2][4][4];
#pragma unroll
    for (int s = 0; s < 2; s++)
#pragma unroll
        for (int f = 0; f < 2; f++)
#pragma unroll
            for (int g = 0; g < 4; g++)
#pragma unroll
                for (int c = 0; c < 4; c++) acc[s][f][g][c] = 0.0f;

#pragma unroll
    for (int ks = 0; ks < 4; ks++) {
        uint32_t ah[2][4], al[2][4];
#pragma unroll
        for (int f = 0; f < 2; f++) {
            int row = mrow + f * 16;
            uint32_t base = sr_u + row * 256;
            int chi = ks * 2 + asel;
            ldsm_x4(base + (((chi    ) ^ (row & 7)) << 4),
                    ah[f][0], ah[f][1], ah[f][2], ah[f][3]);
            ldsm_x4(base + (((chi + 8) ^ (row & 7)) << 4),
                    al[f][0], al[f][1], al[f][2], al[f][3]);
        }
#pragma unroll
        for (int s = 0; s < 2; s++) {
#pragma unroll
            for (int gp = 0; gp < 2; gp++) {
                int brow = s * 64 + wn * 32 + (2 * gp + bg) * 8 + blrow;
                uint32_t bb = km_u + (uint32_t)((brow * PF + bk + ks * 16) * 2);
                uint32_t bh0, bh1, bh2, bh3, bl0, bl1, bl2, bl3;
                ldsm_x4(bb,       bh0, bh1, bh2, bh3);
                ldsm_x4(bb + 128, bl0, bl1, bl2, bl3);
#pragma unroll
                for (int f = 0; f < 2; f++) {
                    mma16816(acc[s][f][2 * gp],     ah[f], bh0, bh1);
                    mma16816(acc[s][f][2 * gp],     al[f], bh0, bh1);
                    mma16816(acc[s][f][2 * gp],     ah[f], bl0, bl1);
                    mma16816(acc[s][f][2 * gp + 1], ah[f], bh2, bh3);
                    mma16816(acc[s][f][2 * gp + 1], al[f], bh2, bh3);
                    mma16816(acc[s][f][2 * gp + 1], ah[f], bl2, bl3);
                }
            }
        }
    }

    __syncthreads();
#pragma unroll
    for (int f = 0; f < 2; f++)
#pragma unroll
        for (int g = 0; g < 4; g++)
#pragma unroll
            for (int c = 0; c < 4; c++) {
                int m = wm * 32 + f * 16 + (lane >> 2) + ((c >> 1) << 3);
                int n = wn * 32 + g * 8 + ((lane & 3) << 1) + (c & 1);
                st[n * STP + m] = ssg[m] * acc[0][f][g][c] + acc[1][f][g][c] + sbias[n];
            }
    __syncthreads();

    const size_t obase = (size_t)b * CH * HWN + p0;
    for (int idx = tid; idx < 2048; idx += 256) {
        int oc = idx >> 5, v = (idx & 31) << 2;
        size_t gi = obase + (size_t)oc * HWN + v;
        float4 xv = *(const float4*)&x[gi];
        float4 sv = *(const float4*)&st[oc * STP + v];
        float4 ov = { xv.x + sv.x, xv.y + sv.y, xv.z + sv.z, xv.w + sv.w };
        *(float4*)&out[gi] = ov;
    }
}

// ---------------- launch ----------------------------------------------------
extern "C" void kernel_launch(void* const* d_in, const int* in_sizes, int n_in,
                              void* d_out, int out_size)
{
    const float* x       = (const float*)d_in[0];
    const float* h       = (const float*)d_in[1];
    const float* conv1_w = (const float*)d_in[2];
    const float* conv1_b = (const float*)d_in[3];
    const float* prelu_a = (const float*)d_in[4];
    const float* conv2_w = (const float*)d_in[5];
    const float* conv2_b = (const float*)d_in[6];
    const float* sa_w    = (const float*)d_in[7];
    const float* sa_b    = (const float*)d_in[8];
    const float* ca_w1   = (const float*)d_in[9];
    const float* ca_b1   = (const float*)d_in[10];
    const float* ca_a    = (const float*)d_in[11];
    const float* ca_w2   = (const float*)d_in[12];
    const float* ca_b2   = (const float*)d_in[13];
    const float* fc_w    = (const float*)d_in[14];
    const float* fc_b    = (const float*)d_in[15];
    const float* k1_w    = (const float*)d_in[16];
    const float* k1_b    = (const float*)d_in[17];
    const float* k2_w    = (const float*)d_in[18];
    const float* k2_b    = (const float*)d_in[19];
    const float* k3_w    = (const float*)d_in[20];
    const float* k3_b    = (const float*)d_in[21];
    const float* hc_bias = (const float*)d_in[22];
    float* out = (float*)d_out;

    __nv_bfloat16 *padx = nullptr, *pad1 = nullptr, *rcl = nullptr;
    uint32_t* wfr = nullptr;
    cudaGetSymbolAddress((void**)&padx, g_padx);
    cudaGetSymbolAddress((void**)&pad1, g_pad1);
    cudaGetSymbolAddress((void**)&rcl,  g_rcl);
    cudaGetSymbolAddress((void**)&wfr,  g_Wfrag);

    static bool attr_set = false;
    if (!attr_set) {
        cudaFuncSetAttribute(conv_frag_kernel<false>,
                             cudaFuncAttributeMaxDynamicSharedMemorySize, STRIP_B);
        cudaFuncSetAttribute(conv_frag_kernel<true>,
                             cudaFuncAttributeMaxDynamicSharedMemorySize, STRIP_B);
        cudaFuncSetAttribute(final_kernel,
                             cudaFuncAttributeMaxDynamicSharedMemorySize, FIN_SMEM);
        attr_set = true;
    }

    init_kernel<<<2, 256>>>();
    wfrag_kernel<<<288, 256>>>(conv1_w, conv2_w);
    pad_input_kernel<<<dim3(256, NB), 256>>>(x);

    dim3 cgrid(IMG_H, NB);
    conv_frag_kernel<false><<<cgrid, 256, STRIP_B>>>(padx, wfr, conv1_b, prelu_a, pad1);
    conv_frag_kernel<true ><<<cgrid, 256, STRIP_B>>>(pad1, wfr + 36864, conv2_b, prelu_a, rcl);

    small_kernel<<<NB, 256>>>(h, ca_w1, ca_b1, ca_a, ca_w2, ca_b2,
                              fc_w, fc_b, k1_w, k1_b, k2_w, k2_b, k3_w, k3_b);

    final_kernel<<<dim3(HWN / 128, NB), 256, FIN_SMEM>>>(hc_bias, sa_w, sa_b, x, out);
}

// round 15
// speedup vs baseline: 2.5017x; 1.5600x over previous
#include <cuda_runtime.h>
#include <cuda_bf16.h>
#include <cuda_fp16.h>
#include <math.h>
#include <float.h>
#include <stdint.h>

#define CH    64
#define IMG_W 256
#define IMG_H 256
#define HWN   65536
#define NB    8
#define PADW  258

// ---------------- device-global scratch -------------------------------------
__device__ __align__(16) __half g_padx[NB * PADW * PADW * 64];   // x, padded, ch-last fp16
__device__ __align__(16) __half g_pad1[NB * PADW * PADW * 64];   // r1, padded, ch-last fp16
__device__ __align__(16) __nv_bfloat16 g_rcl [NB * HWN * 128];   // r, ch-last bf16 hi/lo
__device__ __align__(16) float g_avg[NB * HWN];
__device__ __align__(16) float g_max[NB * HWN];
__device__ float g_chansum[NB * CH];
__device__ __align__(16) __nv_bfloat16 g_Kpk[NB * 2 * 64 * 128];
__device__ __align__(16) uint32_t g_Wfrag[36864];   // fp16 frags [cv][t][wn][ks*2+h][lane][q]

// ---------------- helpers ----------------------------------------------------
__device__ __forceinline__ int reflect(int v, int n) {
    if (v < 0) v = -v;
    if (v >= n) v = 2 * n - 2 - v;
    return v;
}
__device__ __forceinline__ uint32_t s2u(const void* p) {
    return (uint32_t)__cvta_generic_to_shared(p);
}
__device__ __forceinline__ uint32_t pack2bf(float a, float b) {
    return ((uint32_t)__bfloat16_as_ushort(__float2bfloat16(a))) |
           ((uint32_t)__bfloat16_as_ushort(__float2bfloat16(b)) << 16);
}
__device__ __forceinline__ uint32_t pack2h(float a, float b) {
    return ((uint32_t)__half_as_ushort(__float2half(a))) |
           ((uint32_t)__half_as_ushort(__float2half(b)) << 16);
}
__device__ __forceinline__ void ldsm_x4(uint32_t addr, uint32_t& r0, uint32_t& r1,
                                        uint32_t& r2, uint32_t& r3) {
    asm volatile("ldmatrix.sync.aligned.m8n8.x4.shared.b16 {%0,%1,%2,%3}, [%4];"
                 : "=r"(r0), "=r"(r1), "=r"(r2), "=r"(r3) : "r"(addr));
}
// bf16 mma (final kernel)
__device__ __forceinline__ void mma16816(float* c, const uint32_t* a,
                                         uint32_t b0, uint32_t b1) {
    asm volatile("mma.sync.aligned.m16n8k16.row.col.f32.bf16.bf16.f32 "
                 "{%0,%1,%2,%3}, {%4,%5,%6,%7}, {%8,%9}, {%0,%1,%2,%3};"
                 : "+f"(c[0]), "+f"(c[1]), "+f"(c[2]), "+f"(c[3])
                 : "r"(a[0]), "r"(a[1]), "r"(a[2]), "r"(a[3]), "r"(b0), "r"(b1));
}
// fp16 mma (conv kernels)
__device__ __forceinline__ void mma16816h(float* c, const uint32_t* a,
                                          uint32_t b0, uint32_t b1) {
    asm volatile("mma.sync.aligned.m16n8k16.row.col.f32.f16.f16.f32 "
                 "{%0,%1,%2,%3}, {%4,%5,%6,%7}, {%8,%9}, {%0,%1,%2,%3};"
                 : "+f"(c[0]), "+f"(c[1]), "+f"(c[2]), "+f"(c[3])
                 : "r"(a[0]), "r"(a[1]), "r"(a[2]), "r"(a[3]), "r"(b0), "r"(b1));
}
__device__ __forceinline__ void cp16cg(uint32_t dst, const void* src) {
    asm volatile("cp.async.cg.shared.global [%0], [%1], 16;" :: "r"(dst), "l"(src));
}
#define CP_COMMIT() asm volatile("cp.async.commit_group;" ::: "memory")
#define CP_WAIT0()  asm volatile("cp.async.wait_group 0;" ::: "memory")
#define CP_WAIT1()  asm volatile("cp.async.wait_group 1;" ::: "memory")

// ---------------- init ----------------
__global__ void init_kernel() {
    int i = blockIdx.x * blockDim.x + threadIdx.x;
    if (i < NB * CH) g_chansum[i] = 0.0f;
}

// ---------------- weight frag prepack: fp16 single-sweep ---------------------
__global__ __launch_bounds__(256)
void wfrag_kernel(const float* __restrict__ w1, const float* __restrict__ w2) {
    int idx = blockIdx.x * 256 + threadIdx.x;
    if (idx >= 36864) return;
    int q2   = idx & 3;          // ntl*2 + rr
    int lane = (idx >> 2) & 31;
    int fsel = (idx >> 7) & 7;   // ks*2 + h
    int wn   = (idx >> 10) & 1;
    int rest = idx >> 11;        // cv*9 + t
    int t  = rest % 9, cv = rest / 9;
    int rr  = q2 & 1, ntl = q2 >> 1;
    int h   = fsel & 1, ks = fsel >> 1;
    int n  = wn * 32 + (2 * h + ntl) * 8 + (lane >> 2);
    const float* w = cv ? w2 : w1;
    uint32_t out = 0;
#pragma unroll
    for (int e = 0; e < 2; e++) {
        int ch = ks * 16 + rr * 8 + (lane & 3) * 2 + e;
        out |= ((uint32_t)__half_as_ushort(__float2half(w[n * 576 + ch * 9 + t])))
               << (16 * e);
    }
    g_Wfrag[idx] = out;
}

// ---------------- record store with reflect mirrors (8x uint4 = 128B) --------
__device__ __forceinline__ void store_rec_mirror8(uint4* base, int row0, int col0,
                                                  int row1, int col1,
                                                  const uint4* rec) {
    int rows[2] = { row0, row1 };
    int cols[2] = { col0, col1 };
    int nr = (row1 >= 0) ? 2 : 1;
    int nc = (col1 >= 0) ? 2 : 1;
    for (int r = 0; r < nr; r++)
        for (int c = 0; c < nc; c++) {
            uint4* d = base + ((size_t)rows[r] * PADW + cols[c]) * 8;
#pragma unroll
            for (int j = 0; j < 8; j++) d[j] = rec[j];
        }
}

// ---------------- input prepass: fp32 NCHW -> padded ch-last fp16 ------------
__global__ __launch_bounds__(256)
void pad_input_kernel(const float* __restrict__ x) {
    const int y = blockIdx.x, b = blockIdx.y, px = threadIdx.x;
    float v[64];
#pragma unroll
    for (int c = 0; c < 64; c++)
        v[c] = x[(((size_t)(b * 64 + c)) << 16) + y * 256 + px];
    uint4 rec[8];
#pragma unroll
    for (int j = 0; j < 8; j++) {
        int k0 = j * 8;
        uint32_t* wp = (uint32_t*)&rec[j];
#pragma unroll
        for (int q = 0; q < 4; q++)
            wp[q] = pack2h(v[k0 + 2 * q], v[k0 + 2 * q + 1]);
    }
    uint4* base = (uint4*)(g_padx + (size_t)b * PADW * PADW * 64);
    int rmir = (y == 1) ? 0 : (y == 254 ? 257 : -1);
    int cmir = (px == 1) ? 0 : (px == 254 ? 257 : -1);
    store_rec_mirror8(base, y + 1, px + 1, rmir, cmir, rec);
}

// ---------------- conv: fp16 single-sweep mma, M=256/CTA, row double-buffer --
#define HSTRIP_B 33024    // 258 records x 128B
#define CONV_SMEM 66048   // 2 half-strips == st epilogue (64*258*4)

template <bool IS_CONV2>
__global__ __launch_bounds__(256, 2)
void conv_frag_kernel(const __half* __restrict__ pad,
                      const uint32_t* __restrict__ wfrag,
                      const float* __restrict__ bias,
                      const float* __restrict__ prelu_a,
                      void* __restrict__ outp)
{
    extern __shared__ char smem[];
    float* st = (float*)smem;
    __shared__ float s_b[64], s_a[64];

    const int tid = threadIdx.x, lane = tid & 31, wid = tid >> 5;
    const int wm = wid & 3, wn = wid >> 2;
    const int y0 = blockIdx.x, b = blockIdx.y;
    const uint32_t su = s2u(smem);

    if (tid < 64) { s_b[tid] = bias[tid]; s_a[tid] = IS_CONV2 ? 0.f : prelu_a[tid]; }

    float acc[4][4][4];
#pragma unroll
    for (int f = 0; f < 4; f++)
#pragma unroll
        for (int g = 0; g < 4; g++)
#pragma unroll
            for (int c = 0; c < 4; c++) acc[f][g][c] = 0.0f;

    const int mrow = wm * 64 + (lane & 15);
    const int asel = lane >> 4;
    const uint4* wf4 = (const uint4*)wfrag;

    auto stage = [&](int ky) {
        const char* src = (const char*)(pad +
            (((size_t)b * PADW + (y0 + ky)) * PADW) * 64);
        const uint32_t du = su + (ky & 1) * HSTRIP_B;
        for (int i = tid; i < 2064; i += 256) {
            int p = i >> 3, j = i & 7;
            cp16cg(du + p * 128 + ((j ^ (p & 7)) << 4), src + (size_t)i * 16);
        }
        CP_COMMIT();
    };

    stage(0);
    stage(1);

#pragma unroll
    for (int ky = 0; ky < 3; ky++) {
        if (ky < 2) CP_WAIT1(); else CP_WAIT0();
        __syncthreads();
        const uint32_t bu = su + (ky & 1) * HSTRIP_B;
#pragma unroll
        for (int kx = 0; kx < 3; kx++) {
            const uint4* wb = wf4 + ((size_t)(((ky * 3 + kx) * 2 + wn) * 8)) * 32 + lane;
#pragma unroll
            for (int ks = 0; ks < 4; ks++) {
                uint32_t ah[4][4];
#pragma unroll
                for (int f = 0; f < 4; f++) {
                    int row = kx + mrow + f * 16;
                    int chi = ks * 2 + asel;
                    ldsm_x4(bu + row * 128 + (((chi) ^ (row & 7)) << 4),
                            ah[f][0], ah[f][1], ah[f][2], ah[f][3]);
                }
#pragma unroll
                for (int h = 0; h < 2; h++) {
                    uint4 BH = __ldcg(&wb[(ks * 2 + h) * 32]);
                    uint32_t bh[4] = { BH.x, BH.y, BH.z, BH.w };
#pragma unroll
                    for (int gg = 0; gg < 2; gg++) {
                        int g = 2 * h + gg;
#pragma unroll
                        for (int f = 0; f < 4; f++)
                            mma16816h(acc[f][g], ah[f], bh[2 * gg], bh[2 * gg + 1]);
                    }
                }
            }
        }
        if (ky == 0) {           // buf0 consumed -> prefetch row 2 into it
            __syncthreads();
            stage(2);
        }
    }

    // ---- epilogue: transpose via st, emit ch-last records ----
    __syncthreads();
#pragma unroll
    for (int f = 0; f < 4; f++)
#pragma unroll
        for (int g = 0; g < 4; g++)
#pragma unroll
            for (int c = 0; c < 4; c++) {
                int m = wm * 64 + f * 16 + (lane >> 2) + ((c >> 1) << 3);
                int n = wn * 32 + g * 8 + ((lane & 3) << 1) + (c & 1);
                st[n * 258 + m] = acc[f][g][c] + s_b[n];
            }
    __syncthreads();

    {
        float v[64];
#pragma unroll
        for (int c = 0; c < 64; c++) v[c] = st[c * 258 + tid];

        if (!IS_CONV2) {
#pragma unroll
            for (int c = 0; c < 64; c++) v[c] = v[c] > 0.f ? v[c] : s_a[c] * v[c];
            uint4 rec[8];
#pragma unroll
            for (int j = 0; j < 8; j++) {
                int k0 = j * 8;
                uint32_t* wp = (uint32_t*)&rec[j];
#pragma unroll
                for (int q = 0; q < 4; q++)
                    wp[q] = pack2h(v[k0 + 2 * q], v[k0 + 2 * q + 1]);
            }
            uint4* base = (uint4*)((__half*)outp + (size_t)b * PADW * PADW * 64);
            int rmir = (y0 == 1) ? 0 : (y0 == 254 ? 257 : -1);
            int cmir = (tid == 1) ? 0 : (tid == 254 ? 257 : -1);
            store_rec_mirror8(base, y0 + 1, tid + 1, rmir, cmir, rec);
        } else {
            float sum = 0.f, mx = -FLT_MAX;
#pragma unroll
            for (int c = 0; c < 64; c++) { sum += v[c]; mx = fmaxf(mx, v[c]); }
            const int gp = y0 * 256 + tid;
            g_avg[b * HWN + gp] = sum * (1.0f / CH);
            g_max[b * HWN + gp] = mx;
            uint4* dst = (uint4*)((__nv_bfloat16*)outp +
                                  (((size_t)b << 16) + gp) * 128);
#pragma unroll
            for (int j = 0; j < 16; j++) {
                int k0 = (j & 7) * 8;
                bool lo = j >= 8;
                uint4 u; uint32_t* wp = (uint32_t*)&u;
#pragma unroll
                for (int q = 0; q < 4; q++) {
                    float f0 = v[k0 + 2 * q], f1 = v[k0 + 2 * q + 1];
                    if (lo) {
                        f0 -= __bfloat162float(__float2bfloat16(f0));
                        f1 -= __bfloat162float(__float2bfloat16(f1));
                    }
                    wp[q] = pack2bf(f0, f1);
                }
                dst[j] = u;
            }
        }
    }

    if (IS_CONV2) {
        int oc = tid >> 2;
        float s = 0.0f;
        for (int p = (tid & 3); p < 256; p += 4) s += st[oc * 258 + p];
        s += __shfl_xor_sync(0xFFFFFFFFu, s, 1);
        s += __shfl_xor_sync(0xFFFFFFFFu, s, 2);
        if ((tid & 3) == 0) atomicAdd(&g_chansum[b * CH + oc], s);
    }
}

// ---------------- per-batch small dense math + K prepack ---------------------
__global__ __launch_bounds__(256)
void small_kernel(const float* __restrict__ h_in,
                  const float* __restrict__ ca_w1, const float* __restrict__ ca_b1,
                  const float* __restrict__ ca_a,
                  const float* __restrict__ ca_w2, const float* __restrict__ ca_b2,
                  const float* __restrict__ fc_w,  const float* __restrict__ fc_b,
                  const float* __restrict__ k1_w,  const float* __restrict__ k1_b,
                  const float* __restrict__ k2_w,  const float* __restrict__ k2_b,
                  const float* __restrict__ k3_w,  const float* __restrict__ k3_b)
{
    __shared__ float g[64], t1[32], cv[64], hv[16], t0[16], ta[32], tb[32];
    const int b = blockIdx.x;
    const int tid = threadIdx.x;

    if (tid < 64) g[tid] = g_chansum[b * CH + tid] * (1.0f / HWN);
    if (tid < 16) hv[tid] = h_in[b * 16 + tid];
    __syncthreads();

    if (tid < 32) {
        float s = ca_b1[tid];
        for (int c = 0; c < 64; c++) s = fmaf(ca_w1[tid * 64 + c], g[c], s);
        t1[tid] = s > 0.0f ? s : ca_a[tid] * s;
    }
    if (tid >= 32 && tid < 48) {
        int j = tid - 32;
        float s = fc_b[j];
        for (int c = 0; c < 16; c++) s = fmaf(fc_w[j * 16 + c], hv[c], s);
        t0[j] = s >= 0.0f ? s : 0.01f * s;
    }
    __syncthreads();

    if (tid < 64) {
        float s = ca_b2[tid];
        for (int j = 0; j < 32; j++) s = fmaf(ca_w2[tid * 32 + j], t1[j], s);
        cv[tid] = 1.0f / (1.0f + expf(-s));
    }
    if (tid >= 64 && tid < 96) {
        int j = tid - 64;
        float s = k1_b[j];
        for (int c = 0; c < 16; c++) s = fmaf(k1_w[j * 16 + c], t0[c], s);
        ta[j] = s >= 0.0f ? s : 0.01f * s;
    }
    __syncthreads();

    if (tid < 32) {
        float s = k2_b[tid];
        for (int j = 0; j < 32; j++) s = fmaf(k2_w[tid * 32 + j], ta[j], s);
        tb[tid] = s >= 0.0f ? s : 0.01f * s;
    }
    __syncthreads();

    for (int idx = tid; idx < 8192; idx += 256) {
        float s = k3_b[idx];
        for (int j = 0; j < 32; j++) s = fmaf(k3_w[idx * 32 + j], tb[j], s);
        int o = idx >> 7, i = idx & 127;
        int which = (i >= 64);
        int ch = i & 63;
        float val = which ? s * cv[ch] : s;
        __nv_bfloat16 hi = __float2bfloat16(val);
        __nv_bfloat16 lo = __float2bfloat16(val - __bfloat162float(hi));
        size_t base = (size_t)b * 16384 + (which * 64 + o) * 128 + ch;
        g_Kpk[base]      = hi;
        g_Kpk[base + 64] = lo;
    }
}

// ---------------- final: tensor-core dual matvec + fused SA + residual -------
#define PF  136
#define STP 132
#define KM_B   34816
#define SLR_B  32768
#define FIN_SMEM (KM_B + SLR_B + 512)

__global__ __launch_bounds__(256)
void final_kernel(const float* __restrict__ hc_bias,
                  const float* __restrict__ sa_w,
                  const float* __restrict__ sa_b,
                  const float* __restrict__ x,
                  float* __restrict__ out)
{
    extern __shared__ char smem[];
    __nv_bfloat16* sKm = (__nv_bfloat16*)smem;
    char* slabR = smem + KM_B;
    float* ssg = (float*)(smem + KM_B + SLR_B);
    float* st  = (float*)smem;
    __shared__ float sbias[64];

    const int tid  = threadIdx.x;
    const int lane = tid & 31;
    const int wid  = tid >> 5;
    const int wm   = wid & 3;
    const int wn   = wid >> 2;
    const int b    = blockIdx.y;
    const int p0   = blockIdx.x * 128;
    const uint32_t sr_u = s2u(slabR);

    if (tid < 64) sbias[tid] = hc_bias[tid];
    const __nv_bfloat16* ksrc = g_Kpk + (size_t)b * 16384;
    for (int idx = tid; idx < 2048; idx += 256) {
        int r = idx >> 4, v = (idx & 15) << 3;
        *(uint4*)(sKm + r * PF + v) = __ldcg((const uint4*)(ksrc + r * 128 + v));
    }
    {
        const char* src = (const char*)(g_rcl + (((size_t)b << 16) + p0) * 128);
        for (int i = tid; i < 2048; i += 256) {
            int p = i >> 4, j = i & 15;
            cp16cg(sr_u + p * 256 + ((j ^ (p & 7)) << 4), src + (size_t)i * 16);
        }
        CP_COMMIT();
    }
    if (tid < 128) {
        int gp = p0 + tid;
        int xx = gp & (IMG_W - 1);
        int yy = gp >> 8;
        float s = sa_b[0];
#pragma unroll
        for (int ky = 0; ky < 3; ky++) {
            int gy = reflect(yy + ky - 1, IMG_H);
#pragma unroll
            for (int kx = 0; kx < 3; kx++) {
                int gx = reflect(xx + kx - 1, IMG_W);
                int q = b * HWN + gy * IMG_W + gx;
                s = fmaf(sa_w[ky * 3 + kx],     g_avg[q], s);
                s = fmaf(sa_w[9 + ky * 3 + kx], g_max[q], s);
            }
        }
        ssg[tid] = 1.0f / (1.0f + expf(-s));
    }
    CP_WAIT0();
    __syncthreads();

    const uint32_t km_u = s2u(sKm);
    const int mrow = wm * 32 + (lane & 15);
    const int asel = lane >> 4;
    const int bg    = lane >> 4;
    const int bk    = ((lane >> 3) & 1) << 3;
    const int blrow = lane & 7;

    float acc[2][2][4][4];
#pragma unroll
    for (int s = 0; s < 2; s++)
#pragma unroll
        for (int f = 0; f < 2; f++)
#pragma unroll
            for (int g = 0; g < 4; g++)
#pragma unroll
                for (int c = 0; c < 4; c++) acc[s][f][g][c] = 0.0f;

#pragma unroll
    for (int ks = 0; ks < 4; ks++) {
        uint32_t ah[2][4], al[2][4];
#pragma unroll
        for (int f = 0; f < 2; f++) {
            int row = mrow + f * 16;
            uint32_t base = sr_u + row * 256;
            int chi = ks * 2 + asel;
            ldsm_x4(base + (((chi    ) ^ (row & 7)) << 4),
                    ah[f][0], ah[f][1], ah[f][2], ah[f][3]);
            ldsm_x4(base + (((chi + 8) ^ (row & 7)) << 4),
                    al[f][0], al[f][1], al[f][2], al[f][3]);
        }
#pragma unroll
        for (int s = 0; s < 2; s++) {
#pragma unroll
            for (int gp = 0; gp < 2; gp++) {
                int brow = s * 64 + wn * 32 + (2 * gp + bg) * 8 + blrow;
                uint32_t bb = km_u + (uint32_t)((brow * PF + bk + ks * 16) * 2);
                uint32_t bh0, bh1, bh2, bh3, bl0, bl1, bl2, bl3;
                ldsm_x4(bb,       bh0, bh1, bh2, bh3);
                ldsm_x4(bb + 128, bl0, bl1, bl2, bl3);
#pragma unroll
                for (int f = 0; f < 2; f++) {
                    mma16816(acc[s][f][2 * gp],     ah[f], bh0, bh1);
                    mma16816(acc[s][f][2 * gp],     al[f], bh0, bh1);
                    mma16816(acc[s][f][2 * gp],     ah[f], bl0, bl1);
                    mma16816(acc[s][f][2 * gp + 1], ah[f], bh2, bh3);
                    mma16816(acc[s][f][2 * gp + 1], al[f], bh2, bh3);
                    mma16816(acc[s][f][2 * gp + 1], ah[f], bl2, bl3);
                }
            }
        }
    }

    __syncthreads();
#pragma unroll
    for (int f = 0; f < 2; f++)
#pragma unroll
        for (int g = 0; g < 4; g++)
#pragma unroll
            for (int c = 0; c < 4; c++) {
                int m = wm * 32 + f * 16 + (lane >> 2) + ((c >> 1) << 3);
                int n = wn * 32 + g * 8 + ((lane & 3) << 1) + (c & 1);
                st[n * STP + m] = ssg[m] * acc[0][f][g][c] + acc[1][f][g][c] + sbias[n];
            }
    __syncthreads();

    const size_t obase = (size_t)b * CH * HWN + p0;
    for (int idx = tid; idx < 2048; idx += 256) {
        int oc = idx >> 5, v = (idx & 31) << 2;
        size_t gi = obase + (size_t)oc * HWN + v;
        float4 xv = *(const float4*)&x[gi];
        float4 sv = *(const float4*)&st[oc * STP + v];
        float4 ov = { xv.x + sv.x, xv.y + sv.y, xv.z + sv.z, xv.w + sv.w };
        *(float4*)&out[gi] = ov;
    }
}

// ---------------- launch ----------------------------------------------------
extern "C" void kernel_launch(void* const* d_in, const int* in_sizes, int n_in,
                              void* d_out, int out_size)
{
    const float* x       = (const float*)d_in[0];
    const float* h       = (const float*)d_in[1];
    const float* conv1_w = (const float*)d_in[2];
    const float* conv1_b = (const float*)d_in[3];
    const float* prelu_a = (const float*)d_in[4];
    const float* conv2_w = (const float*)d_in[5];
    const float* conv2_b = (const float*)d_in[6];
    const float* sa_w    = (const float*)d_in[7];
    const float* sa_b    = (const float*)d_in[8];
    const float* ca_w1   = (const float*)d_in[9];
    const float* ca_b1   = (const float*)d_in[10];
    const float* ca_a    = (const float*)d_in[11];
    const float* ca_w2   = (const float*)d_in[12];
    const float* ca_b2   = (const float*)d_in[13];
    const float* fc_w    = (const float*)d_in[14];
    const float* fc_b    = (const float*)d_in[15];
    const float* k1_w    = (const float*)d_in[16];
    const float* k1_b    = (const float*)d_in[17];
    const float* k2_w    = (const float*)d_in[18];
    const float* k2_b    = (const float*)d_in[19];
    const float* k3_w    = (const float*)d_in[20];
    const float* k3_b    = (const float*)d_in[21];
    const float* hc_bias = (const float*)d_in[22];
    float* out = (float*)d_out;

    __half *padx = nullptr, *pad1 = nullptr;
    __nv_bfloat16* rcl = nullptr;
    uint32_t* wfr = nullptr;
    cudaGetSymbolAddress((void**)&padx, g_padx);
    cudaGetSymbolAddress((void**)&pad1, g_pad1);
    cudaGetSymbolAddress((void**)&rcl,  g_rcl);
    cudaGetSymbolAddress((void**)&wfr,  g_Wfrag);

    static bool attr_set = false;
    if (!attr_set) {
        cudaFuncSetAttribute(conv_frag_kernel<false>,
                             cudaFuncAttributeMaxDynamicSharedMemorySize, CONV_SMEM);
        cudaFuncSetAttribute(conv_frag_kernel<true>,
                             cudaFuncAttributeMaxDynamicSharedMemorySize, CONV_SMEM);
        cudaFuncSetAttribute(final_kernel,
                             cudaFuncAttributeMaxDynamicSharedMemorySize, FIN_SMEM);
        attr_set = true;
    }

    init_kernel<<<2, 256>>>();
    wfrag_kernel<<<144, 256>>>(conv1_w, conv2_w);
    pad_input_kernel<<<dim3(256, NB), 256>>>(x);

    dim3 cgrid(IMG_H, NB);
    conv_frag_kernel<false><<<cgrid, 256, CONV_SMEM>>>(padx, wfr,         conv1_b, prelu_a, pad1);
    conv_frag_kernel<true ><<<cgrid, 256, CONV_SMEM>>>(pad1, wfr + 18432, conv2_b, prelu_a, rcl);

    small_kernel<<<NB, 256>>>(h, ca_w1, ca_b1, ca_a, ca_w2, ca_b2,
                              fc_w, fc_b, k1_w, k1_b, k2_w, k2_b, k3_w, k3_b);

    final_kernel<<<dim3(HWN / 128, NB), 256, FIN_SMEM>>>(hc_bias, sa_w, sa_b, x, out);
}

// round 16
// speedup vs baseline: 2.7709x; 1.1076x over previous
#include <cuda_runtime.h>
#include <cuda_bf16.h>
#include <cuda_fp16.h>
#include <math.h>
#include <float.h>
#include <stdint.h>

#define CH    64
#define IMG_W 256
#define IMG_H 256
#define HWN   65536
#define NB    8
#define PADW  258

// ---------------- device-global scratch -------------------------------------
__device__ __align__(16) __half g_padx[NB * PADW * PADW * 64];   // x, padded, ch-last fp16
__device__ __align__(16) __half g_pad1[NB * PADW * PADW * 64];   // r1, padded, ch-last fp16
__device__ __align__(16) __half g_rcl [NB * HWN * 64];           // r, ch-last fp16
__device__ __align__(16) float g_avg[NB * HWN];
__device__ __align__(16) float g_max[NB * HWN];
__device__ float g_chansum[NB * CH];
__device__ __align__(16) __half g_Kpk[NB * 2 * 64 * 64];         // K matrices, fp16
__device__ __align__(16) uint32_t g_Wfrag[36864];   // fp16 frags [cv][t][wn][ks*2+h][lane][q]

// ---------------- helpers ----------------------------------------------------
__device__ __forceinline__ int reflect(int v, int n) {
    if (v < 0) v = -v;
    if (v >= n) v = 2 * n - 2 - v;
    return v;
}
__device__ __forceinline__ uint32_t s2u(const void* p) {
    return (uint32_t)__cvta_generic_to_shared(p);
}
__device__ __forceinline__ uint32_t pack2h(float a, float b) {
    return ((uint32_t)__half_as_ushort(__float2half(a))) |
           ((uint32_t)__half_as_ushort(__float2half(b)) << 16);
}
__device__ __forceinline__ void ldsm_x4(uint32_t addr, uint32_t& r0, uint32_t& r1,
                                        uint32_t& r2, uint32_t& r3) {
    asm volatile("ldmatrix.sync.aligned.m8n8.x4.shared.b16 {%0,%1,%2,%3}, [%4];"
                 : "=r"(r0), "=r"(r1), "=r"(r2), "=r"(r3) : "r"(addr));
}
__device__ __forceinline__ void mma16816h(float* c, const uint32_t* a,
                                          uint32_t b0, uint32_t b1) {
    asm volatile("mma.sync.aligned.m16n8k16.row.col.f32.f16.f16.f32 "
                 "{%0,%1,%2,%3}, {%4,%5,%6,%7}, {%8,%9}, {%0,%1,%2,%3};"
                 : "+f"(c[0]), "+f"(c[1]), "+f"(c[2]), "+f"(c[3])
                 : "r"(a[0]), "r"(a[1]), "r"(a[2]), "r"(a[3]), "r"(b0), "r"(b1));
}
__device__ __forceinline__ void cp16cg(uint32_t dst, const void* src) {
    asm volatile("cp.async.cg.shared.global [%0], [%1], 16;" :: "r"(dst), "l"(src));
}
#define CP_COMMIT() asm volatile("cp.async.commit_group;" ::: "memory")
#define CP_WAIT0()  asm volatile("cp.async.wait_group 0;" ::: "memory")
#define CP_WAIT1()  asm volatile("cp.async.wait_group 1;" ::: "memory")

// ---------------- init ----------------
__global__ void init_kernel() {
    int i = blockIdx.x * blockDim.x + threadIdx.x;
    if (i < NB * CH) g_chansum[i] = 0.0f;
}

// ---------------- weight frag prepack: fp16 single-sweep ---------------------
__global__ __launch_bounds__(256)
void wfrag_kernel(const float* __restrict__ w1, const float* __restrict__ w2) {
    int idx = blockIdx.x * 256 + threadIdx.x;
    if (idx >= 36864) return;
    int q2   = idx & 3;          // ntl*2 + rr
    int lane = (idx >> 2) & 31;
    int fsel = (idx >> 7) & 7;   // ks*2 + h
    int wn   = (idx >> 10) & 1;
    int rest = idx >> 11;        // cv*9 + t
    int t  = rest % 9, cv = rest / 9;
    int rr  = q2 & 1, ntl = q2 >> 1;
    int h   = fsel & 1, ks = fsel >> 1;
    int n  = wn * 32 + (2 * h + ntl) * 8 + (lane >> 2);
    const float* w = cv ? w2 : w1;
    uint32_t out = 0;
#pragma unroll
    for (int e = 0; e < 2; e++) {
        int ch = ks * 16 + rr * 8 + (lane & 3) * 2 + e;
        out |= ((uint32_t)__half_as_ushort(__float2half(w[n * 576 + ch * 9 + t])))
               << (16 * e);
    }
    g_Wfrag[idx] = out;
}

// ---------------- record store with reflect mirrors (8x uint4 = 128B) --------
__device__ __forceinline__ void store_rec_mirror8(uint4* base, int row0, int col0,
                                                  int row1, int col1,
                                                  const uint4* rec) {
    int rows[2] = { row0, row1 };
    int cols[2] = { col0, col1 };
    int nr = (row1 >= 0) ? 2 : 1;
    int nc = (col1 >= 0) ? 2 : 1;
    for (int r = 0; r < nr; r++)
        for (int c = 0; c < nc; c++) {
            uint4* d = base + ((size_t)rows[r] * PADW + cols[c]) * 8;
#pragma unroll
            for (int j = 0; j < 8; j++) d[j] = rec[j];
        }
}

// ---------------- input prepass: fp32 NCHW -> padded ch-last fp16 ------------
__global__ __launch_bounds__(256)
void pad_input_kernel(const float* __restrict__ x) {
    const int y = blockIdx.x, b = blockIdx.y, px = threadIdx.x;
    float v[64];
#pragma unroll
    for (int c = 0; c < 64; c++)
        v[c] = x[(((size_t)(b * 64 + c)) << 16) + y * 256 + px];
    uint4 rec[8];
#pragma unroll
    for (int j = 0; j < 8; j++) {
        int k0 = j * 8;
        uint32_t* wp = (uint32_t*)&rec[j];
#pragma unroll
        for (int q = 0; q < 4; q++)
            wp[q] = pack2h(v[k0 + 2 * q], v[k0 + 2 * q + 1]);
    }
    uint4* base = (uint4*)(g_padx + (size_t)b * PADW * PADW * 64);
    int rmir = (y == 1) ? 0 : (y == 254 ? 257 : -1);
    int cmir = (px == 1) ? 0 : (px == 254 ? 257 : -1);
    store_rec_mirror8(base, y + 1, px + 1, rmir, cmir, rec);
}

// ---------------- conv: fp16 single-sweep mma, M=256/CTA, row double-buffer --
#define HSTRIP_B 33024    // 258 records x 128B
#define CONV_SMEM 66048

template <bool IS_CONV2>
__global__ __launch_bounds__(256, 2)
void conv_frag_kernel(const __half* __restrict__ pad,
                      const uint32_t* __restrict__ wfrag,
                      const float* __restrict__ bias,
                      const float* __restrict__ prelu_a,
                      __half* __restrict__ outp)
{
    extern __shared__ char smem[];
    float* st = (float*)smem;
    __shared__ float s_b[64], s_a[64];

    const int tid = threadIdx.x, lane = tid & 31, wid = tid >> 5;
    const int wm = wid & 3, wn = wid >> 2;
    const int y0 = blockIdx.x, b = blockIdx.y;
    const uint32_t su = s2u(smem);

    if (tid < 64) { s_b[tid] = bias[tid]; s_a[tid] = IS_CONV2 ? 0.f : prelu_a[tid]; }

    float acc[4][4][4];
#pragma unroll
    for (int f = 0; f < 4; f++)
#pragma unroll
        for (int g = 0; g < 4; g++)
#pragma unroll
            for (int c = 0; c < 4; c++) acc[f][g][c] = 0.0f;

    const int mrow = wm * 64 + (lane & 15);
    const int asel = lane >> 4;
    const uint4* wf4 = (const uint4*)wfrag;

    auto stage = [&](int ky) {
        const char* src = (const char*)(pad +
            (((size_t)b * PADW + (y0 + ky)) * PADW) * 64);
        const uint32_t du = su + (ky & 1) * HSTRIP_B;
        for (int i = tid; i < 2064; i += 256) {
            int p = i >> 3, j = i & 7;
            cp16cg(du + p * 128 + ((j ^ (p & 7)) << 4), src + (size_t)i * 16);
        }
        CP_COMMIT();
    };

    stage(0);
    stage(1);

#pragma unroll
    for (int ky = 0; ky < 3; ky++) {
        if (ky < 2) CP_WAIT1(); else CP_WAIT0();
        __syncthreads();
        const uint32_t bu = su + (ky & 1) * HSTRIP_B;
#pragma unroll
        for (int kx = 0; kx < 3; kx++) {
            const uint4* wb = wf4 + ((size_t)(((ky * 3 + kx) * 2 + wn) * 8)) * 32 + lane;
#pragma unroll
            for (int ks = 0; ks < 4; ks++) {
                uint32_t ah[4][4];
#pragma unroll
                for (int f = 0; f < 4; f++) {
                    int row = kx + mrow + f * 16;
                    int chi = ks * 2 + asel;
                    ldsm_x4(bu + row * 128 + (((chi) ^ (row & 7)) << 4),
                            ah[f][0], ah[f][1], ah[f][2], ah[f][3]);
                }
#pragma unroll
                for (int h = 0; h < 2; h++) {
                    uint4 BH = __ldcg(&wb[(ks * 2 + h) * 32]);
                    uint32_t bh[4] = { BH.x, BH.y, BH.z, BH.w };
#pragma unroll
                    for (int gg = 0; gg < 2; gg++) {
                        int g = 2 * h + gg;
#pragma unroll
                        for (int f = 0; f < 4; f++)
                            mma16816h(acc[f][g], ah[f], bh[2 * gg], bh[2 * gg + 1]);
                    }
                }
            }
        }
        if (ky == 0) {
            __syncthreads();
            stage(2);
        }
    }

    // ---- epilogue: transpose via st, emit ch-last fp16 records ----
    __syncthreads();
#pragma unroll
    for (int f = 0; f < 4; f++)
#pragma unroll
        for (int g = 0; g < 4; g++)
#pragma unroll
            for (int c = 0; c < 4; c++) {
                int m = wm * 64 + f * 16 + (lane >> 2) + ((c >> 1) << 3);
                int n = wn * 32 + g * 8 + ((lane & 3) << 1) + (c & 1);
                st[n * 258 + m] = acc[f][g][c] + s_b[n];
            }
    __syncthreads();

    {
        float v[64];
#pragma unroll
        for (int c = 0; c < 64; c++) v[c] = st[c * 258 + tid];

        if (!IS_CONV2) {
#pragma unroll
            for (int c = 0; c < 64; c++) v[c] = v[c] > 0.f ? v[c] : s_a[c] * v[c];
        } else {
            float sum = 0.f, mx = -FLT_MAX;
#pragma unroll
            for (int c = 0; c < 64; c++) { sum += v[c]; mx = fmaxf(mx, v[c]); }
            const int gp = y0 * 256 + tid;
            g_avg[b * HWN + gp] = sum * (1.0f / CH);
            g_max[b * HWN + gp] = mx;
        }

        uint4 rec[8];
#pragma unroll
        for (int j = 0; j < 8; j++) {
            int k0 = j * 8;
            uint32_t* wp = (uint32_t*)&rec[j];
#pragma unroll
            for (int q = 0; q < 4; q++)
                wp[q] = pack2h(v[k0 + 2 * q], v[k0 + 2 * q + 1]);
        }

        if (!IS_CONV2) {
            uint4* base = (uint4*)(outp + (size_t)b * PADW * PADW * 64);
            int rmir = (y0 == 1) ? 0 : (y0 == 254 ? 257 : -1);
            int cmir = (tid == 1) ? 0 : (tid == 254 ? 257 : -1);
            store_rec_mirror8(base, y0 + 1, tid + 1, rmir, cmir, rec);
        } else {
            uint4* dst = (uint4*)(outp + (((size_t)b << 16) + y0 * 256 + tid) * 64);
#pragma unroll
            for (int j = 0; j < 8; j++) dst[j] = rec[j];
        }
    }

    if (IS_CONV2) {
        int oc = tid >> 2;
        float s = 0.0f;
        for (int p = (tid & 3); p < 256; p += 4) s += st[oc * 258 + p];
        s += __shfl_xor_sync(0xFFFFFFFFu, s, 1);
        s += __shfl_xor_sync(0xFFFFFFFFu, s, 2);
        if ((tid & 3) == 0) atomicAdd(&g_chansum[b * CH + oc], s);
    }
}

// ---------------- per-batch small dense math + K prepack (fp16) --------------
__global__ __launch_bounds__(256)
void small_kernel(const float* __restrict__ h_in,
                  const float* __restrict__ ca_w1, const float* __restrict__ ca_b1,
                  const float* __restrict__ ca_a,
                  const float* __restrict__ ca_w2, const float* __restrict__ ca_b2,
                  const float* __restrict__ fc_w,  const float* __restrict__ fc_b,
                  const float* __restrict__ k1_w,  const float* __restrict__ k1_b,
                  const float* __restrict__ k2_w,  const float* __restrict__ k2_b,
                  const float* __restrict__ k3_w,  const float* __restrict__ k3_b)
{
    __shared__ float g[64], t1[32], cv[64], hv[16], t0[16], ta[32], tb[32];
    const int b = blockIdx.x;
    const int tid = threadIdx.x;

    if (tid < 64) g[tid] = g_chansum[b * CH + tid] * (1.0f / HWN);
    if (tid < 16) hv[tid] = h_in[b * 16 + tid];
    __syncthreads();

    if (tid < 32) {
        float s = ca_b1[tid];
        for (int c = 0; c < 64; c++) s = fmaf(ca_w1[tid * 64 + c], g[c], s);
        t1[tid] = s > 0.0f ? s : ca_a[tid] * s;
    }
    if (tid >= 32 && tid < 48) {
        int j = tid - 32;
        float s = fc_b[j];
        for (int c = 0; c < 16; c++) s = fmaf(fc_w[j * 16 + c], hv[c], s);
        t0[j] = s >= 0.0f ? s : 0.01f * s;
    }
    __syncthreads();

    if (tid < 64) {
        float s = ca_b2[tid];
        for (int j = 0; j < 32; j++) s = fmaf(ca_w2[tid * 32 + j], t1[j], s);
        cv[tid] = 1.0f / (1.0f + expf(-s));
    }
    if (tid >= 64 && tid < 96) {
        int j = tid - 64;
        float s = k1_b[j];
        for (int c = 0; c < 16; c++) s = fmaf(k1_w[j * 16 + c], t0[c], s);
        ta[j] = s >= 0.0f ? s : 0.01f * s;
    }
    __syncthreads();

    if (tid < 32) {
        float s = k2_b[tid];
        for (int j = 0; j < 32; j++) s = fmaf(k2_w[tid * 32 + j], ta[j], s);
        tb[tid] = s >= 0.0f ? s : 0.01f * s;
    }
    __syncthreads();

    for (int idx = tid; idx < 8192; idx += 256) {
        float s = k3_b[idx];
        for (int j = 0; j < 32; j++) s = fmaf(k3_w[idx * 32 + j], tb[j], s);
        int o = idx >> 7, i = idx & 127;
        int which = (i >= 64);
        int ch = i & 63;
        float val = which ? s * cv[ch] : s;
        g_Kpk[(size_t)b * 8192 + (which * 64 + o) * 64 + ch] = __float2half(val);
    }
}

// ---------------- final: fp16 dual matvec + fused SA + residual --------------
#define STP 132
#define KM_B   16384
#define SLR_B  16384
#define SSG_OFF 34048
#define FIN_SMEM 34560

__global__ __launch_bounds__(256)
void final_kernel(const float* __restrict__ hc_bias,
                  const float* __restrict__ sa_w,
                  const float* __restrict__ sa_b,
                  const float* __restrict__ x,
                  float* __restrict__ out)
{
    extern __shared__ char smem[];
    char* sKm   = smem;                     // 128 K-rows x 128B, swizzled
    char* slabR = smem + KM_B;              // 128 px records x 128B, swizzled
    float* ssg  = (float*)(smem + SSG_OFF); // [128] (beyond st region)
    float* st   = (float*)smem;             // epilogue reuse (33792B)
    __shared__ float sbias[64];

    const int tid  = threadIdx.x;
    const int lane = tid & 31;
    const int wid  = tid >> 5;
    const int wm   = wid & 3;
    const int wn   = wid >> 2;
    const int b    = blockIdx.y;
    const int p0   = blockIdx.x * 128;
    const uint32_t km_u = s2u(sKm);
    const uint32_t sr_u = s2u(slabR);

    if (tid < 64) sbias[tid] = hc_bias[tid];
    {
        const char* ks = (const char*)(g_Kpk + (size_t)b * 8192);
        const char* rs = (const char*)(g_rcl + (((size_t)b << 16) + p0) * 64);
        for (int i = tid; i < 1024; i += 256) {
            int p = i >> 3, j = i & 7;
            cp16cg(km_u + p * 128 + ((j ^ (p & 7)) << 4), ks + (size_t)i * 16);
        }
        for (int i = tid; i < 1024; i += 256) {
            int p = i >> 3, j = i & 7;
            cp16cg(sr_u + p * 128 + ((j ^ (p & 7)) << 4), rs + (size_t)i * 16);
        }
        CP_COMMIT();
    }
    if (tid < 128) {
        int gp = p0 + tid;
        int xx = gp & (IMG_W - 1);
        int yy = gp >> 8;
        float s = sa_b[0];
#pragma unroll
        for (int ky = 0; ky < 3; ky++) {
            int gy = reflect(yy + ky - 1, IMG_H);
#pragma unroll
            for (int kx = 0; kx < 3; kx++) {
                int gx = reflect(xx + kx - 1, IMG_W);
                int q = b * HWN + gy * IMG_W + gx;
                s = fmaf(sa_w[ky * 3 + kx],     g_avg[q], s);
                s = fmaf(sa_w[9 + ky * 3 + kx], g_max[q], s);
            }
        }
        ssg[tid] = 1.0f / (1.0f + expf(-s));
    }
    CP_WAIT0();
    __syncthreads();

    const int mrow  = wm * 32 + (lane & 15);
    const int asel  = lane >> 4;
    const int bg    = lane >> 4;
    const int bkbit = (lane >> 3) & 1;
    const int blrow = lane & 7;

    float acc[2][2][4][4];
#pragma unroll
    for (int s = 0; s < 2; s++)
#pragma unroll
        for (int f = 0; f < 2; f++)
#pragma unroll
            for (int g = 0; g < 4; g++)
#pragma unroll
                for (int c = 0; c < 4; c++) acc[s][f][g][c] = 0.0f;

#pragma unroll
    for (int ks = 0; ks < 4; ks++) {
        uint32_t ah[2][4];
#pragma unroll
        for (int f = 0; f < 2; f++) {
            int row = mrow + f * 16;
            int chi = ks * 2 + asel;
            ldsm_x4(sr_u + row * 128 + ((chi ^ (row & 7)) << 4),
                    ah[f][0], ah[f][1], ah[f][2], ah[f][3]);
        }
#pragma unroll
        for (int s = 0; s < 2; s++) {
#pragma unroll
            for (int gp = 0; gp < 2; gp++) {
                int brow = s * 64 + wn * 32 + (2 * gp + bg) * 8 + blrow;
                int chib = ks * 2 + bkbit;
                uint32_t b0, b1, b2, b3;
                ldsm_x4(km_u + brow * 128 + ((chib ^ (brow & 7)) << 4),
                        b0, b1, b2, b3);
#pragma unroll
                for (int f = 0; f < 2; f++) {
                    mma16816h(acc[s][f][2 * gp],     ah[f], b0, b1);
                    mma16816h(acc[s][f][2 * gp + 1], ah[f], b2, b3);
                }
            }
        }
    }

    __syncthreads();
#pragma unroll
    for (int f = 0; f < 2; f++)
#pragma unroll
        for (int g = 0; g < 4; g++)
#pragma unroll
            for (int c = 0; c < 4; c++) {
                int m = wm * 32 + f * 16 + (lane >> 2) + ((c >> 1) << 3);
                int n = wn * 32 + g * 8 + ((lane & 3) << 1) + (c & 1);
                st[n * STP + m] = ssg[m] * acc[0][f][g][c] + acc[1][f][g][c] + sbias[n];
            }
    __syncthreads();

    const size_t obase = (size_t)b * CH * HWN + p0;
    for (int idx = tid; idx < 2048; idx += 256) {
        int oc = idx >> 5, v = (idx & 31) << 2;
        size_t gi = obase + (size_t)oc * HWN + v;
        float4 xv = *(const float4*)&x[gi];
        float4 sv = *(const float4*)&st[oc * STP + v];
        float4 ov = { xv.x + sv.x, xv.y + sv.y, xv.z + sv.z, xv.w + sv.w };
        *(float4*)&out[gi] = ov;
    }
}

// ---------------- launch ----------------------------------------------------
extern "C" void kernel_launch(void* const* d_in, const int* in_sizes, int n_in,
                              void* d_out, int out_size)
{
    const float* x       = (const float*)d_in[0];
    const float* h       = (const float*)d_in[1];
    const float* conv1_w = (const float*)d_in[2];
    const float* conv1_b = (const float*)d_in[3];
    const float* prelu_a = (const float*)d_in[4];
    const float* conv2_w = (const float*)d_in[5];
    const float* conv2_b = (const float*)d_in[6];
    const float* sa_w    = (const float*)d_in[7];
    const float* sa_b    = (const float*)d_in[8];
    const float* ca_w1   = (const float*)d_in[9];
    const float* ca_b1   = (const float*)d_in[10];
    const float* ca_a    = (const float*)d_in[11];
    const float* ca_w2   = (const float*)d_in[12];
    const float* ca_b2   = (const float*)d_in[13];
    const float* fc_w    = (const float*)d_in[14];
    const float* fc_b    = (const float*)d_in[15];
    const float* k1_w    = (const float*)d_in[16];
    const float* k1_b    = (const float*)d_in[17];
    const float* k2_w    = (const float*)d_in[18];
    const float* k2_b    = (const float*)d_in[19];
    const float* k3_w    = (const float*)d_in[20];
    const float* k3_b    = (const float*)d_in[21];
    const float* hc_bias = (const float*)d_in[22];
    float* out = (float*)d_out;

    __half *padx = nullptr, *pad1 = nullptr, *rcl = nullptr;
    uint32_t* wfr = nullptr;
    cudaGetSymbolAddress((void**)&padx, g_padx);
    cudaGetSymbolAddress((void**)&pad1, g_pad1);
    cudaGetSymbolAddress((void**)&rcl,  g_rcl);
    cudaGetSymbolAddress((void**)&wfr,  g_Wfrag);

    static bool attr_set = false;
    if (!attr_set) {
        cudaFuncSetAttribute(conv_frag_kernel<false>,
                             cudaFuncAttributeMaxDynamicSharedMemorySize, CONV_SMEM);
        cudaFuncSetAttribute(conv_frag_kernel<true>,
                             cudaFuncAttributeMaxDynamicSharedMemorySize, CONV_SMEM);
        cudaFuncSetAttribute(final_kernel,
                             cudaFuncAttributeMaxDynamicSharedMemorySize, FIN_SMEM);
        attr_set = true;
    }

    init_kernel<<<2, 256>>>();
    wfrag_kernel<<<144, 256>>>(conv1_w, conv2_w);
    pad_input_kernel<<<dim3(256, NB), 256>>>(x);

    dim3 cgrid(IMG_H, NB);
    conv_frag_kernel<false><<<cgrid, 256, CONV_SMEM>>>(padx, wfr,         conv1_b, prelu_a, pad1);
    conv_frag_kernel<true ><<<cgrid, 256, CONV_SMEM>>>(pad1, wfr + 18432, conv2_b, prelu_a, rcl);

    small_kernel<<<NB, 256>>>(h, ca_w1, ca_b1, ca_a, ca_w2, ca_b2,
                              fc_w, fc_b, k1_w, k1_b, k2_w, k2_b, k3_w, k3_b);

    final_kernel<<<dim3(HWN / 128, NB), 256, FIN_SMEM>>>(hc_bias, sa_w, sa_b, x, out);
}